// round 5
// baseline (speedup 1.0000x reference)
#include <cuda_runtime.h>
#include <cstdint>

typedef unsigned long long ull;

#define Bz   16
#define L1x  512
#define L2x  512
#define EMB  300
#define AH   256
#define KIN  816          // padded 812
#define NR   768          // 3 * 256 (padded 250)
#define MR   16384        // B*L1 + B*L2
#define RNNK 1280
#define NG   1024
#define HH   128

// ---------------- scratch ----------------
__device__ float  g_Abig[MR * KIN];
__device__ float  g_Wbig[NR * KIN];
__device__ float  g_vbig[NR];
__device__ float  g_R[MR * NR];
__device__ float  g_S[48 * L1x * L2x];
__device__ float  g_X1CAT[8192 * RNNK];
__device__ float  g_X2V[3 * Bz * L2x * AH];
__device__ float  g_Wih[NG * RNNK];
__device__ float  g_bias[NG];
__device__ float  g_G[8192 * NG];
__device__ float4 g_WhhP4[2 * 32 * 512];

// ---------------- f32x2 helpers ----------------
__device__ __forceinline__ ull pack2(float lo, float hi) {
    ull r; asm("mov.b64 %0, {%1, %2};" : "=l"(r) : "f"(lo), "f"(hi)); return r;
}
__device__ __forceinline__ void unpack2(ull v, float& lo, float& hi) {
    asm("mov.b64 {%0, %1}, %2;" : "=f"(lo), "=f"(hi) : "l"(v));
}
__device__ __forceinline__ void ffma2(ull& d, ull a, ull b) {
    asm("fma.rn.f32x2 %0, %1, %2, %0;" : "+l"(d) : "l"(a), "l"(b));
}
__device__ __forceinline__ ull addf2(ull a, ull b) {
    ull r; asm("add.rn.f32x2 %0, %1, %2;" : "=l"(r) : "l"(a), "l"(b)); return r;
}

// ---------------- prep kernels ----------------
__global__ void prep_A(const float* __restrict__ x1w, const float* __restrict__ x1a0,
                       const float* __restrict__ x1a1, const float* __restrict__ x2w,
                       const float* __restrict__ x2a0, const float* __restrict__ x2a1) {
    int idx = blockIdx.x * 256 + threadIdx.x;
    if (idx >= MR * KIN) return;
    int r = idx / KIN, c = idx - r * KIN;
    float v = 0.f;
    if (c < 812) {
        int half = r >> 13;
        int bl   = r & 8191;
        if (c < 300) {
            const float* w = half ? x2w : x1w;
            v = w[(size_t)bl * EMB + c];
        } else if (c < 556) {
            const float* a0 = half ? x2a0 : x1a0;
            v = a0[(size_t)bl * AH + (c - 300)];
        } else {
            const float* a1 = half ? x2a1 : x1a1;
            v = a1[(size_t)bl * AH + (c - 556)];
        }
    }
    g_Abig[idx] = v;
}

__global__ void prep_W(const float* __restrict__ Wattn, const float* __restrict__ vattn) {
    int idx = blockIdx.x * 256 + threadIdx.x;
    if (idx >= NR * KIN) return;
    int g = idx / KIN, c = idx - g * KIN;
    int i = g >> 8, a = g & 255;
    g_Wbig[idx] = (a < 250 && c < 812) ? Wattn[((size_t)(i * 250 + a)) * 812 + c] : 0.f;
    if (idx < NR) {
        int i2 = idx >> 8, a2 = idx & 255;
        g_vbig[idx] = (a2 < 250) ? vattn[i2 * 250 + a2] : 0.f;
    }
}

__global__ void prep_Wih(const float* __restrict__ Wf, const float* __restrict__ Wb,
                         const float* __restrict__ bf, const float* __restrict__ bb) {
    int idx = blockIdx.x * 256 + threadIdx.x;
    if (idx >= NG * RNNK) return;
    int r = idx / RNNK, c = idx - r * RNNK;
    g_Wih[idx] = (r < 512) ? Wf[(size_t)r * RNNK + c] : Wb[(size_t)(r - 512) * RNNK + c];
    if (idx < NG) g_bias[idx] = (idx < 512) ? bf[idx] : bb[idx - 512];
}

__global__ void prep_X2V(const float* __restrict__ a0, const float* __restrict__ a1,
                         const float* __restrict__ a2) {
    int idx = blockIdx.x * 256 + threadIdx.x;
    if (idx >= 3 * Bz * L2x * AH) return;
    int i = idx / (Bz * L2x * AH);
    int rest = idx - i * (Bz * L2x * AH);
    const float* s = (i == 0) ? a0 : (i == 1) ? a1 : a2;
    g_X2V[idx] = s[rest];
}

__global__ void prep_head(const float* __restrict__ x1a0, const float* __restrict__ x1a1) {
    int idx = blockIdx.x * 256 + threadIdx.x;
    if (idx >= 8192 * 512) return;
    int r = idx >> 9, c = idx & 511;
    g_X1CAT[(size_t)r * RNNK + c] = (c < 256) ? x1a0[(size_t)r * AH + c]
                                              : x1a1[(size_t)r * AH + (c - 256)];
}

__global__ void prep_Whh(const float* __restrict__ Whhf, const float* __restrict__ Whhb) {
    int idx = blockIdx.x * 256 + threadIdx.x;
    if (idx >= 2 * 32 * 512) return;
    int d = idx >> 14, k4 = (idx >> 9) & 31, g = idx & 511;
    const float* s = d ? Whhb : Whhf;
    size_t base = (size_t)g * HH + k4 * 4;
    g_WhhP4[idx] = make_float4(s[base], s[base + 1], s[base + 2], s[base + 3]);
}

// ---------------- GEMM ----------------
// C[M,N] = A[M,K] * op(B).  BNN==0: B is [N,K] (NT).  BNN==1: B is [K,N] (NN).
// EPI: 0 none; 1 relu, and *evec[n] for rows >= rowSplit; 2 +evec[n].
// Tiles: 128x128x16. Smem k-major with pad 132.
template <int BNN, int EPI>
__global__ void __launch_bounds__(256, 2)
gemm_kernel(const float* __restrict__ A, const float* __restrict__ B, float* __restrict__ C,
            int K, int lda, int ldb, int ldc, int zdiv,
            long sAb, long sAi, long sBb, long sBi, long sCb, long sCi,
            const float* __restrict__ evec, int rowSplit) {
    __shared__ float As[2][16][132];
    __shared__ float Bs[2][16][132];
    const int z  = blockIdx.z;
    const int zi = z % zdiv, zb = z / zdiv;
    A += zb * sAb + zi * sAi;
    B += zb * sBb + zi * sBi;
    C += zb * sCb + zi * sCi;
    const int m0 = blockIdx.y * 128, n0 = blockIdx.x * 128;
    const int tid = threadIdx.x;
    const int cn = tid & 15, rm = tid >> 4;
    const int ar = tid >> 2, ac = tid & 3;       // transpose loader (A, NT-B)
    const int kr = tid >> 5, ncl = tid & 31;     // NN-B loader

    ull acc[8][4];
#pragma unroll
    for (int i = 0; i < 8; i++)
#pragma unroll
        for (int j = 0; j < 4; j++) acc[i][j] = 0ull;

    const int nk = K >> 4;
    float4 ra0, ra1, rb0, rb1;

    {   // prologue loads, tile 0
        const float* pa = A + (size_t)(m0 + ar) * lda + ac * 4;
        ra0 = *(const float4*)pa;
        ra1 = *(const float4*)(pa + (size_t)64 * lda);
        if (BNN == 0) {
            const float* pb = B + (size_t)(n0 + ar) * ldb + ac * 4;
            rb0 = *(const float4*)pb;
            rb1 = *(const float4*)(pb + (size_t)64 * ldb);
        } else {
            const float* pb = B + (size_t)kr * ldb + n0 + ncl * 4;
            rb0 = *(const float4*)pb;
            rb1 = *(const float4*)(pb + (size_t)8 * ldb);
        }
    }
    {
        As[0][ac*4+0][ar] = ra0.x; As[0][ac*4+1][ar] = ra0.y;
        As[0][ac*4+2][ar] = ra0.z; As[0][ac*4+3][ar] = ra0.w;
        As[0][ac*4+0][ar+64] = ra1.x; As[0][ac*4+1][ar+64] = ra1.y;
        As[0][ac*4+2][ar+64] = ra1.z; As[0][ac*4+3][ar+64] = ra1.w;
        if (BNN == 0) {
            Bs[0][ac*4+0][ar] = rb0.x; Bs[0][ac*4+1][ar] = rb0.y;
            Bs[0][ac*4+2][ar] = rb0.z; Bs[0][ac*4+3][ar] = rb0.w;
            Bs[0][ac*4+0][ar+64] = rb1.x; Bs[0][ac*4+1][ar+64] = rb1.y;
            Bs[0][ac*4+2][ar+64] = rb1.z; Bs[0][ac*4+3][ar+64] = rb1.w;
        } else {
            *(float4*)&Bs[0][kr][ncl*4]     = rb0;
            *(float4*)&Bs[0][kr+8][ncl*4]   = rb1;
        }
    }
    __syncthreads();

    for (int kt = 0; kt < nk; ++kt) {
        const int cur = kt & 1;
        if (kt + 1 < nk) {
            const int k1 = (kt + 1) << 4;
            const float* pa = A + (size_t)(m0 + ar) * lda + k1 + ac * 4;
            ra0 = *(const float4*)pa;
            ra1 = *(const float4*)(pa + (size_t)64 * lda);
            if (BNN == 0) {
                const float* pb = B + (size_t)(n0 + ar) * ldb + k1 + ac * 4;
                rb0 = *(const float4*)pb;
                rb1 = *(const float4*)(pb + (size_t)64 * ldb);
            } else {
                const float* pb = B + (size_t)(k1 + kr) * ldb + n0 + ncl * 4;
                rb0 = *(const float4*)pb;
                rb1 = *(const float4*)(pb + (size_t)8 * ldb);
            }
        }
#pragma unroll
        for (int kk = 0; kk < 16; ++kk) {
            float4 a0 = *(const float4*)&As[cur][kk][rm * 4];
            float4 a1 = *(const float4*)&As[cur][kk][64 + rm * 4];
            float4 b0 = *(const float4*)&Bs[cur][kk][cn * 4];
            float4 b1 = *(const float4*)&Bs[cur][kk][64 + cn * 4];
            ull bp0 = pack2(b0.x, b0.y), bp1 = pack2(b0.z, b0.w);
            ull bp2 = pack2(b1.x, b1.y), bp3 = pack2(b1.z, b1.w);
            float am[8] = {a0.x, a0.y, a0.z, a0.w, a1.x, a1.y, a1.z, a1.w};
#pragma unroll
            for (int mi = 0; mi < 8; ++mi) {
                ull ad = pack2(am[mi], am[mi]);
                ffma2(acc[mi][0], ad, bp0);
                ffma2(acc[mi][1], ad, bp1);
                ffma2(acc[mi][2], ad, bp2);
                ffma2(acc[mi][3], ad, bp3);
            }
        }
        if (kt + 1 < nk) {
            const int nxt = cur ^ 1;
            __syncthreads();
            As[nxt][ac*4+0][ar] = ra0.x; As[nxt][ac*4+1][ar] = ra0.y;
            As[nxt][ac*4+2][ar] = ra0.z; As[nxt][ac*4+3][ar] = ra0.w;
            As[nxt][ac*4+0][ar+64] = ra1.x; As[nxt][ac*4+1][ar+64] = ra1.y;
            As[nxt][ac*4+2][ar+64] = ra1.z; As[nxt][ac*4+3][ar+64] = ra1.w;
            if (BNN == 0) {
                Bs[nxt][ac*4+0][ar] = rb0.x; Bs[nxt][ac*4+1][ar] = rb0.y;
                Bs[nxt][ac*4+2][ar] = rb0.z; Bs[nxt][ac*4+3][ar] = rb0.w;
                Bs[nxt][ac*4+0][ar+64] = rb1.x; Bs[nxt][ac*4+1][ar+64] = rb1.y;
                Bs[nxt][ac*4+2][ar+64] = rb1.z; Bs[nxt][ac*4+3][ar+64] = rb1.w;
            } else {
                *(float4*)&Bs[nxt][kr][ncl*4]   = rb0;
                *(float4*)&Bs[nxt][kr+8][ncl*4] = rb1;
            }
            __syncthreads();
        }
    }

#pragma unroll
    for (int mi = 0; mi < 8; ++mi) {
        int mrow = (mi < 4) ? (rm * 4 + mi) : (64 + rm * 4 + mi - 4);
        int mg = m0 + mrow;
        float o[8];
        unpack2(acc[mi][0], o[0], o[1]); unpack2(acc[mi][1], o[2], o[3]);
        unpack2(acc[mi][2], o[4], o[5]); unpack2(acc[mi][3], o[6], o[7]);
        int c0 = n0 + cn * 4, c1 = n0 + 64 + cn * 4;
        if (EPI == 1) {
#pragma unroll
            for (int j = 0; j < 8; j++) o[j] = fmaxf(o[j], 0.f);
            if (mg >= rowSplit) {
                o[0] *= evec[c0]; o[1] *= evec[c0+1]; o[2] *= evec[c0+2]; o[3] *= evec[c0+3];
                o[4] *= evec[c1]; o[5] *= evec[c1+1]; o[6] *= evec[c1+2]; o[7] *= evec[c1+3];
            }
        } else if (EPI == 2) {
            o[0] += evec[c0]; o[1] += evec[c0+1]; o[2] += evec[c0+2]; o[3] += evec[c0+3];
            o[4] += evec[c1]; o[5] += evec[c1+1]; o[6] += evec[c1+2]; o[7] += evec[c1+3];
        }
        *(float4*)(C + (size_t)mg * ldc + c0) = make_float4(o[0], o[1], o[2], o[3]);
        *(float4*)(C + (size_t)mg * ldc + c1) = make_float4(o[4], o[5], o[6], o[7]);
    }
}

// ---------------- softmax over rows of 512 (in place, with mask) ----------------
__global__ void softmax_kernel(float* __restrict__ S, const unsigned char* __restrict__ x2mask) {
    const float NEGF = -3.4e38f;
    float2* row = (float2*)(S + (size_t)blockIdx.x * 512);
    int b = blockIdx.x / 1536;       // blockIdx.x = (b*3+i)*512 + l
    const unsigned char* mk = x2mask + b * 512;
    int t = threadIdx.x;
    float2 v = row[t];
    if (mk[2*t])   v.x = NEGF;
    if (mk[2*t+1]) v.y = NEGF;
    __shared__ float red[8];
    float mx = fmaxf(v.x, v.y);
#pragma unroll
    for (int o = 16; o; o >>= 1) mx = fmaxf(mx, __shfl_xor_sync(0xffffffffu, mx, o));
    if ((t & 31) == 0) red[t >> 5] = mx;
    __syncthreads();
    float M = red[0];
#pragma unroll
    for (int i = 1; i < 8; i++) M = fmaxf(M, red[i]);
    __syncthreads();
    float e0 = __expf(v.x - M), e1 = __expf(v.y - M);
    float s = e0 + e1;
#pragma unroll
    for (int o = 16; o; o >>= 1) s += __shfl_xor_sync(0xffffffffu, s, o);
    if ((t & 31) == 0) red[t >> 5] = s;
    __syncthreads();
    float tot = red[0];
#pragma unroll
    for (int i = 1; i < 8; i++) tot += red[i];
    float inv = __fdividef(1.f, tot);
    row[t] = make_float2(e0 * inv, e1 * inv);
}

// ---------------- BiLSTM ----------------
__device__ __forceinline__ float sigf(float x) {
    return __fdividef(1.f, 1.f + __expf(-x));
}
__device__ __forceinline__ float tanhf_fast(float x) {
    return 1.f - __fdividef(2.f, __expf(2.f * x) + 1.f);
}

#define LSTM_SMEM (16 * 512 * 16 + 512 * 4 + 128 * 4)   // 133632 B

__global__ void __launch_bounds__(512, 1)
lstm_kernel(const float* __restrict__ G, float* __restrict__ out) {
    extern __shared__ char smraw[];
    float4* W4  = (float4*)smraw;                      // [16][512] float4 (k4 0..15)
    float* zbuf = (float*)(smraw + 16 * 512 * 16);
    float* hs   = zbuf + 512;                          // 128 floats, 16B aligned

    const int dir = blockIdx.x & 1;
    const int b   = blockIdx.x >> 1;
    const int g   = threadIdx.x;

    const float4* Wg = g_WhhP4 + (size_t)dir * 32 * 512;
    for (int i = g; i < 16 * 512; i += 512) W4[i] = Wg[i];
    ull wr[32];
#pragma unroll
    for (int j = 0; j < 16; j++) {
        float4 w = Wg[(16 + j) * 512 + g];
        wr[2*j]   = pack2(w.x, w.y);
        wr[2*j+1] = pack2(w.z, w.w);
    }
    if (g < 128) hs[g] = 0.f;
    float c = 0.f;
    __syncthreads();

    const float* gptr = G + (size_t)b * 512 * NG + dir * 512 + g;
    int trow  = dir ? 511 : 0;
    const int tstep = dir ? -1 : 1;
    float gv = gptr[(size_t)trow * NG];

    for (int t = 0; t < 512; ++t) {
        float gcur = gv;
        if (t + 1 < 512) gv = gptr[(size_t)(trow + tstep) * NG];

        ull acc0 = 0ull, acc1 = 0ull;
#pragma unroll
        for (int k4 = 0; k4 < 16; k4++) {
            float4 w = W4[k4 * 512 + g];
            float4 h = *((const float4*)(hs + k4 * 4));
            ffma2(acc0, pack2(w.x, w.y), pack2(h.x, h.y));
            ffma2(acc1, pack2(w.z, w.w), pack2(h.z, h.w));
        }
#pragma unroll
        for (int j = 0; j < 16; j++) {
            float4 h = *((const float4*)(hs + (16 + j) * 4));
            ffma2(acc0, wr[2*j],   pack2(h.x, h.y));
            ffma2(acc1, wr[2*j+1], pack2(h.z, h.w));
        }
        ull a = addf2(acc0, acc1);
        float lo, hi; unpack2(a, lo, hi);
        zbuf[g] = lo + hi + gcur;
        __syncthreads();

        if (g < 128) {
            float zi = zbuf[g], zf = zbuf[g + 128], zg = zbuf[g + 256], zo = zbuf[g + 384];
            c = sigf(zf) * c + sigf(zi) * tanhf_fast(zg);
            float h = sigf(zo) * tanhf_fast(c);
            hs[g] = h;
            out[((size_t)b * 512 + trow) * 256 + dir * 128 + g] = h;
        }
        __syncthreads();
        trow += tstep;
    }
}

// ---------------- launch ----------------
extern "C" void kernel_launch(void* const* d_in, const int* in_sizes, int n_in,
                              void* d_out, int out_size) {
    const float* x1w  = (const float*)d_in[0];
    const float* x1a0 = (const float*)d_in[1];
    const float* x1a1 = (const float*)d_in[2];
    const float* x2w  = (const float*)d_in[3];
    const float* x2a0 = (const float*)d_in[4];
    const float* x2a1 = (const float*)d_in[5];
    const float* x2a2 = (const float*)d_in[6];
    const unsigned char* x2mask = (const unsigned char*)d_in[8];
    const float* Wattn = (const float*)d_in[9];
    const float* vattn = (const float*)d_in[10];
    const float* Wihf = (const float*)d_in[11];
    const float* Whhf = (const float*)d_in[12];
    const float* bf   = (const float*)d_in[13];
    const float* Wihb = (const float*)d_in[14];
    const float* Whhb = (const float*)d_in[15];
    const float* bb   = (const float*)d_in[16];
    float* out = (float*)d_out;

    static bool attr_done = false;
    if (!attr_done) {
        cudaFuncSetAttribute(lstm_kernel, cudaFuncAttributeMaxDynamicSharedMemorySize, LSTM_SMEM);
        attr_done = true;
    }

    // device-global symbol addresses
    float *Abig, *Wbig, *vbig, *R, *S, *X1, *X2V, *Wih, *bias, *Gm;
    float4* WhhP;
    cudaGetSymbolAddress((void**)&Abig, g_Abig);
    cudaGetSymbolAddress((void**)&Wbig, g_Wbig);
    cudaGetSymbolAddress((void**)&vbig, g_vbig);
    cudaGetSymbolAddress((void**)&R,    g_R);
    cudaGetSymbolAddress((void**)&S,    g_S);
    cudaGetSymbolAddress((void**)&X1,   g_X1CAT);
    cudaGetSymbolAddress((void**)&X2V,  g_X2V);
    cudaGetSymbolAddress((void**)&Wih,  g_Wih);
    cudaGetSymbolAddress((void**)&bias, g_bias);
    cudaGetSymbolAddress((void**)&Gm,   g_G);
    cudaGetSymbolAddress((void**)&WhhP, g_WhhP4);

    // prep
    prep_A   <<<(MR * KIN + 255) / 256, 256>>>(x1w, x1a0, x1a1, x2w, x2a0, x2a1);
    prep_W   <<<(NR * KIN + 255) / 256, 256>>>(Wattn, vattn);
    prep_Wih <<<(NG * RNNK + 255) / 256, 256>>>(Wihf, Wihb, bf, bb);
    prep_X2V <<<(3 * Bz * L2x * AH + 255) / 256, 256>>>(x2a0, x2a1, x2a2);
    prep_head<<<(8192 * 512 + 255) / 256, 256>>>(x1a0, x1a1);
    prep_Whh <<<(2 * 32 * 512 + 255) / 256, 256>>>(Whhf, Whhb);

    // R = relu(Abig * Wbig^T), x2 rows scaled by v
    {
        dim3 grid(NR / 128, MR / 128, 1);
        gemm_kernel<0, 1><<<grid, 256>>>(Abig, Wbig, R, KIN, KIN, KIN, NR, 1,
                                         0, 0, 0, 0, 0, 0, vbig, 8192);
    }
    // scores: per (b,i): S = r1 * r2^T   [512x512x256]
    {
        dim3 grid(512 / 128, 512 / 128, 48);
        gemm_kernel<0, 0><<<grid, 256>>>(R, R + (size_t)8192 * NR, S, 256, NR, NR, 512, 3,
                                         (long)512 * NR, 256,
                                         (long)512 * NR, 256,
                                         (long)3 * 512 * 512, (long)512 * 512,
                                         nullptr, 0);
    }
    // softmax rows
    softmax_kernel<<<48 * 512, 256>>>(S, x2mask);
    // attn: per (b,i): X1[:, 512+i*256 : +256] = alpha * x2_i   [512x256x512], NN
    {
        dim3 grid(256 / 128, 512 / 128, 48);
        gemm_kernel<1, 0><<<grid, 256>>>(S, X2V, X1 + 512, 512, 512, AH, RNNK, 3,
                                         (long)3 * 512 * 512, (long)512 * 512,
                                         (long)L2x * AH, (long)Bz * L2x * AH,
                                         (long)512 * RNNK, 256,
                                         nullptr, 0);
    }
    // g_in = X1 * Wih^T + bias   [8192x1024x1280]
    {
        dim3 grid(NG / 128, 8192 / 128, 1);
        gemm_kernel<0, 2><<<grid, 256>>>(X1, Wih, Gm, RNNK, RNNK, RNNK, NG, 1,
                                         0, 0, 0, 0, 0, 0, bias, 0);
    }
    // BiLSTM
    lstm_kernel<<<32, 512, LSTM_SMEM>>>(Gm, out);
}

// round 7
// speedup vs baseline: 1.4462x; 1.4462x over previous
#include <cuda_runtime.h>
#include <cuda_fp16.h>
#include <cstdint>

typedef unsigned long long ull;

#define Bz   16
#define EMB  300
#define AH   256
#define KPADR 832              // padded 812 -> 832 (13*64)
#define NR   768               // 3*256
#define MR   16384
#define RNNK 1280
#define NG   1024
#define HH   128

// ---- scratch (fp16 split, concatenated-K: A-side=[hi|hi|lo], B-side=[hi|lo|hi]) ----
__device__ __half g_A3 [MR * (3*KPADR)];        // 16384 x 2496
__device__ __half g_W3 [NR * (3*KPADR)];        // 768 x 2496
__device__ float  g_vbig[NR];
__device__ __half g_R3A[8192 * (3*NR)];         // x1 rows, pattern A, 8192 x 2304
__device__ __half g_R3B[8192 * (3*NR)];         // x2 rows (v-scaled), pattern B
__device__ float  g_S  [48 * 512 * 512];
__device__ __half g_AL3[48 * 512 * (3*512)];    // alpha split, pattern A
__device__ __half g_X2T3[48 * 256 * (3*512)];   // x2^T split, pattern B, rows (i*16+b)*256+d
__device__ __half g_X13[8192 * (3*RNNK)];       // X1CAT split, pattern A, 8192 x 3840
__device__ __half g_Wih3[NG * (3*RNNK)];        // pattern B, 1024 x 3840
__device__ float  g_bias[NG];
__device__ float  g_G  [8192 * NG];
__device__ float4 g_WhhP4[2 * 32 * 512];

// ---- f32x2 helpers (LSTM) ----
__device__ __forceinline__ ull pack2(float lo, float hi) {
    ull r; asm("mov.b64 %0, {%1, %2};" : "=l"(r) : "f"(lo), "f"(hi)); return r;
}
__device__ __forceinline__ void unpack2(ull v, float& lo, float& hi) {
    asm("mov.b64 {%0, %1}, %2;" : "=f"(lo), "=f"(hi) : "l"(v));
}
__device__ __forceinline__ void ffma2(ull& d, ull a, ull b) {
    asm("fma.rn.f32x2 %0, %1, %2, %0;" : "+l"(d) : "l"(a), "l"(b));
}
__device__ __forceinline__ ull addf2(ull a, ull b) {
    ull r; asm("add.rn.f32x2 %0, %1, %2;" : "=l"(r) : "l"(a), "l"(b)); return r;
}
__device__ __forceinline__ uint32_t s2u(const void* p) {
    uint32_t a;
    asm("{ .reg .u64 t; cvta.to.shared.u64 t, %1; cvt.u32.u64 %0, t; }" : "=r"(a) : "l"(p));
    return a;
}
__device__ __forceinline__ void split_h(float v, __half& h, __half& l) {
    h = __float2half_rn(v);
    l = __float2half_rn(v - __half2float(h));
}
__device__ __forceinline__ uint32_t swz(uint32_t off) {
    return off ^ ((off >> 3) & 0x70);
}
__device__ __forceinline__ void cp16(uint32_t dst, const void* src) {
    asm volatile("cp.async.cg.shared.global [%0], [%1], 16;" :: "r"(dst), "l"(src));
}
__device__ __forceinline__ void ldm_x4(uint32_t* r, uint32_t addr) {
    asm volatile("ldmatrix.sync.aligned.m8n8.x4.shared.b16 {%0,%1,%2,%3}, [%4];"
                 : "=r"(r[0]), "=r"(r[1]), "=r"(r[2]), "=r"(r[3]) : "r"(addr));
}
__device__ __forceinline__ void mma16816(float* c, const uint32_t* a, const uint32_t* b) {
    asm volatile(
        "mma.sync.aligned.m16n8k16.row.col.f32.f16.f16.f32 "
        "{%0,%1,%2,%3}, {%4,%5,%6,%7}, {%8,%9}, {%0,%1,%2,%3};"
        : "+f"(c[0]), "+f"(c[1]), "+f"(c[2]), "+f"(c[3])
        : "r"(a[0]), "r"(a[1]), "r"(a[2]), "r"(a[3]), "r"(b[0]), "r"(b[1]));
}

// ---------------- prep kernels ----------------
__global__ void prep_A3(const float* __restrict__ x1w, const float* __restrict__ x1a0,
                        const float* __restrict__ x1a1, const float* __restrict__ x2w,
                        const float* __restrict__ x2a0, const float* __restrict__ x2a1) {
    int idx = blockIdx.x * 256 + threadIdx.x;
    if (idx >= MR * KPADR) return;
    int r = idx / KPADR, c = idx - r * KPADR;
    float v = 0.f;
    if (c < 812) {
        int half = r >> 13, bl = r & 8191;
        if (c < 300)       v = (half ? x2w  : x1w )[(size_t)bl * EMB + c];
        else if (c < 556)  v = (half ? x2a0 : x1a0)[(size_t)bl * AH + (c - 300)];
        else               v = (half ? x2a1 : x1a1)[(size_t)bl * AH + (c - 556)];
    }
    __half h, l; split_h(v, h, l);
    __half* row = g_A3 + (size_t)r * (3 * KPADR) + c;
    row[0] = h; row[KPADR] = h; row[2 * KPADR] = l;    // pattern A
}

__global__ void prep_W3(const float* __restrict__ Wattn, const float* __restrict__ vattn) {
    int idx = blockIdx.x * 256 + threadIdx.x;
    if (idx >= NR * KPADR) return;
    int g = idx / KPADR, c = idx - g * KPADR;
    int i = g >> 8, a = g & 255;
    float v = (a < 250 && c < 812) ? Wattn[((size_t)(i * 250 + a)) * 812 + c] : 0.f;
    __half h, l; split_h(v, h, l);
    __half* row = g_W3 + (size_t)g * (3 * KPADR) + c;
    row[0] = h; row[KPADR] = l; row[2 * KPADR] = h;    // pattern B
    if (idx < NR) {
        int i2 = idx >> 8, a2 = idx & 255;
        g_vbig[idx] = (a2 < 250) ? vattn[i2 * 250 + a2] : 0.f;
    }
}

__global__ void prep_Wih3(const float* __restrict__ Wf, const float* __restrict__ Wb,
                          const float* __restrict__ bf, const float* __restrict__ bb) {
    int idx = blockIdx.x * 256 + threadIdx.x;
    if (idx >= NG * RNNK) return;
    int r = idx / RNNK, c = idx - r * RNNK;
    float v = (r < 512) ? Wf[(size_t)r * RNNK + c] : Wb[(size_t)(r - 512) * RNNK + c];
    __half h, l; split_h(v, h, l);
    __half* row = g_Wih3 + (size_t)r * (3 * RNNK) + c;
    row[0] = h; row[RNNK] = l; row[2 * RNNK] = h;      // pattern B
    if (idx < NG) g_bias[idx] = (idx < 512) ? bf[idx] : bb[idx - 512];
}

__global__ void prep_headX13(const float* __restrict__ x1a0, const float* __restrict__ x1a1) {
    int idx = blockIdx.x * 256 + threadIdx.x;
    if (idx >= 8192 * 512) return;
    int r = idx >> 9, c = idx & 511;
    float v = (c < 256) ? x1a0[(size_t)r * AH + c] : x1a1[(size_t)r * AH + (c - 256)];
    __half h, l; split_h(v, h, l);
    __half* row = g_X13 + (size_t)r * (3 * RNNK) + c;
    row[0] = h; row[RNNK] = h; row[2 * RNNK] = l;      // pattern A
}

// transpose x2_abstr_i [b][s][d] -> X2T3 rows (i*16+b)*256+d, cols s; split pattern B
__global__ void prep_X2T3(const float* __restrict__ a0, const float* __restrict__ a1,
                          const float* __restrict__ a2) {
    __shared__ float tile[32][33];
    int i = blockIdx.z >> 4, b = blockIdx.z & 15;
    int s0 = blockIdx.x * 32, d0 = blockIdx.y * 32;
    int tx = threadIdx.x, ty = threadIdx.y;
    const float* src = (i == 0) ? a0 : (i == 1) ? a1 : a2;
    tile[ty][tx] = src[((size_t)(b * 512 + s0 + ty)) * 256 + d0 + tx];
    __syncthreads();
    float v = tile[tx][ty];
    __half h, l; split_h(v, h, l);
    __half* row = g_X2T3 + ((size_t)((i * 16 + b) * 256 + d0 + ty)) * 1536 + s0 + tx;
    row[0] = h; row[512] = l; row[1024] = h;           // pattern B
}

__global__ void prep_Whh(const float* __restrict__ Whhf, const float* __restrict__ Whhb) {
    int idx = blockIdx.x * 256 + threadIdx.x;
    if (idx >= 2 * 32 * 512) return;
    int d = idx >> 14, k4 = (idx >> 9) & 31, g = idx & 511;
    const float* s = d ? Whhb : Whhf;
    size_t base = (size_t)g * HH + k4 * 4;
    g_WhhP4[idx] = make_float4(s[base], s[base + 1], s[base + 2], s[base + 3]);
}

// ---------------- HMMA GEMM: C[M,N] = A[M,K'] * B[N,K'] (fp16 NT, fp32 accum) ----------------
// 128x128 CTA tile, k-chunks of 64, cp.async double buffer, 8 warps (warp tile 32x64).
// EPI: 0 scores f32 | 1 R split-out relu(+v) | 2 gin f32+bias | 3 X13 split-out
#define HG_SMEM (2 * 32768)

template <int EPI>
__global__ void __launch_bounds__(256, 2)
hgemm(const __half* __restrict__ A, const __half* __restrict__ B,
      float* __restrict__ Cf, __half* __restrict__ Cb,
      int ldA, int ldB, int ldC, int nkc, int kcPerSec, int secStride,
      int zdiv, long sAb, long sAi, long sBb, long sBi, long sCb, long sCi,
      const float* __restrict__ evec, int rowSplit) {
    extern __shared__ __align__(1024) char smem[];
    const uint32_t su = s2u(smem);
    const int tid = threadIdx.x, lane = tid & 31, wid = tid >> 5;

    const int z = blockIdx.z, zi = z % zdiv, zb = z / zdiv;
    A += zb * sAb + zi * sAi;
    B += zb * sBb + zi * sBi;
    if (EPI == 0 || EPI == 2) Cf += zb * sCb + zi * sCi;
    if (EPI == 3)             Cb += zb * sCb + zi * sCi;
    const int m0 = blockIdx.y * 128, n0 = blockIdx.x * 128;
    const int r0 = tid >> 3, c16 = tid & 7;

    float acc[2][8][4];
#pragma unroll
    for (int i = 0; i < 2; i++)
#pragma unroll
        for (int j = 0; j < 8; j++)
#pragma unroll
            for (int q = 0; q < 4; q++) acc[i][j][q] = 0.f;

    const int wm = wid & 3, wn = wid >> 2;
    const int a_row = wm * 32 + (lane & 15);
    const int a_kb  = (lane >> 4) * 8;
    const int b_row = wn * 64 + ((lane >> 4) << 3) + (lane & 7);
    const int b_kb  = ((lane >> 3) & 1) * 8;

    // issue chunk kc into buffer bsel
    auto issue = [&](int kc, int bsel) {
        int sec = kc / kcPerSec;
        int colBase = sec * secStride + (kc - sec * kcPerSec) * 64;
        const __half* Ag = A + (size_t)(m0 + r0) * ldA + colBase + c16 * 8;
        const __half* Bg = B + (size_t)(n0 + r0) * ldB + colBase + c16 * 8;
        uint32_t sbase = su + bsel * 32768;
#pragma unroll
        for (int j = 0; j < 4; ++j) {
            uint32_t off = swz((r0 + 32 * j) * 128 + c16 * 16);
            cp16(sbase + off,          Ag + (size_t)(32 * j) * ldA);
            cp16(sbase + 16384 + off,  Bg + (size_t)(32 * j) * ldB);
        }
        asm volatile("cp.async.commit_group;" ::: "memory");
    };

    issue(0, 0);
    for (int kc = 0; kc < nkc; ++kc) {
        const int bsel = kc & 1;
        asm volatile("cp.async.wait_group 0;" ::: "memory");
        __syncthreads();
        if (kc + 1 < nkc) issue(kc + 1, bsel ^ 1);
        const uint32_t sAu = su + bsel * 32768;
        const uint32_t sBu = sAu + 16384;
#pragma unroll
        for (int ks = 0; ks < 4; ++ks) {
            uint32_t af[2][4], bf[4][4];
#pragma unroll
            for (int mi = 0; mi < 2; ++mi) {
                uint32_t off = (uint32_t)(a_row + mi * 16) * 128 + (a_kb + ks * 16) * 2;
                ldm_x4(af[mi], sAu + swz(off));
            }
#pragma unroll
            for (int nj = 0; nj < 4; ++nj) {
                uint32_t off = (uint32_t)(b_row + nj * 16) * 128 + (b_kb + ks * 16) * 2;
                ldm_x4(bf[nj], sBu + swz(off));
            }
#pragma unroll
            for (int mi = 0; mi < 2; ++mi)
#pragma unroll
                for (int ni = 0; ni < 8; ++ni)
                    mma16816(acc[mi][ni], af[mi], &bf[ni >> 1][(ni & 1) * 2]);
        }
    }

    // epilogue
    const int tq = lane >> 2, tr = (lane & 3) * 2;
#pragma unroll
    for (int mi = 0; mi < 2; ++mi) {
#pragma unroll
        for (int h = 0; h < 2; ++h) {
            const int mg = m0 + wm * 32 + mi * 16 + h * 8 + tq;
#pragma unroll
            for (int ni = 0; ni < 8; ++ni) {
                const int nc = n0 + wn * 64 + ni * 8 + tr;
                float v0 = acc[mi][ni][h * 2], v1 = acc[mi][ni][h * 2 + 1];
                if (EPI == 0) {
                    *(float2*)(Cf + (size_t)mg * ldC + nc) = make_float2(v0, v1);
                } else if (EPI == 2) {
                    *(float2*)(Cf + (size_t)mg * ldC + nc) =
                        make_float2(v0 + evec[nc], v1 + evec[nc + 1]);
                } else if (EPI == 1) {
                    const bool isB = (mg >= rowSplit);
                    v0 = fmaxf(v0, 0.f); v1 = fmaxf(v1, 0.f);
                    if (isB) { v0 *= evec[nc]; v1 *= evec[nc + 1]; }
                    __half h0, l0, h1, l1;
                    split_h(v0, h0, l0); split_h(v1, h1, l1);
                    __half2 hh = __halves2half2(h0, h1);
                    __half2 ll = __halves2half2(l0, l1);
                    __half* base = isB ? g_R3B + (size_t)(mg - rowSplit) * (3 * NR) + nc
                                       : g_R3A + (size_t)mg * (3 * NR) + nc;
                    *(__half2*)(base)              = hh;
                    *(__half2*)(base + NR)         = isB ? ll : hh;
                    *(__half2*)(base + 2 * NR)     = isB ? hh : ll;
                } else {  // EPI == 3
                    __half h0, l0, h1, l1;
                    split_h(v0, h0, l0); split_h(v1, h1, l1);
                    __half2 hh = __halves2half2(h0, h1);
                    __half2 ll = __halves2half2(l0, l1);
                    __half* base = Cb + (size_t)mg * (3 * RNNK) + nc;
                    *(__half2*)(base)              = hh;
                    *(__half2*)(base + RNNK)       = hh;
                    *(__half2*)(base + 2 * RNNK)   = ll;
                }
            }
        }
    }
}

// ---------------- softmax: rows of 512 -> split fp16 alpha (pattern A) ----------------
__global__ void softmax_kernel(const float* __restrict__ S, const unsigned char* __restrict__ x2mask) {
    const float NEGF = -3.4e38f;
    const float2* row = (const float2*)(S + (size_t)blockIdx.x * 512);
    int b = blockIdx.x / 1536;
    const unsigned char* mk = x2mask + b * 512;
    int t = threadIdx.x;
    float2 v = row[t];
    if (mk[2 * t])     v.x = NEGF;
    if (mk[2 * t + 1]) v.y = NEGF;
    __shared__ float red[8];
    float mx = fmaxf(v.x, v.y);
#pragma unroll
    for (int o = 16; o; o >>= 1) mx = fmaxf(mx, __shfl_xor_sync(0xffffffffu, mx, o));
    if ((t & 31) == 0) red[t >> 5] = mx;
    __syncthreads();
    float M = red[0];
#pragma unroll
    for (int i = 1; i < 8; i++) M = fmaxf(M, red[i]);
    __syncthreads();
    float e0 = __expf(v.x - M), e1 = __expf(v.y - M);
    float s = e0 + e1;
#pragma unroll
    for (int o = 16; o; o >>= 1) s += __shfl_xor_sync(0xffffffffu, s, o);
    if ((t & 31) == 0) red[t >> 5] = s;
    __syncthreads();
    float tot = red[0];
#pragma unroll
    for (int i = 1; i < 8; i++) tot += red[i];
    float inv = __fdividef(1.f, tot);
    float p0 = e0 * inv, p1 = e1 * inv;
    __half h0, l0, h1, l1;
    split_h(p0, h0, l0); split_h(p1, h1, l1);
    __half2 hh = __halves2half2(h0, h1);
    __half2 ll = __halves2half2(l0, l1);
    __half* base = g_AL3 + (size_t)blockIdx.x * 1536 + 2 * t;
    *(__half2*)(base)        = hh;
    *(__half2*)(base + 512)  = hh;
    *(__half2*)(base + 1024) = ll;
}

// ---------------- BiLSTM (fp32, f32x2 — unchanged from R5 passing version) ----------------
__device__ __forceinline__ float sigf(float x) { return __fdividef(1.f, 1.f + __expf(-x)); }
__device__ __forceinline__ float tanhf_fast(float x) { return 1.f - __fdividef(2.f, __expf(2.f * x) + 1.f); }

#define LSTM_SMEM (16 * 512 * 16 + 512 * 4 + 128 * 4)

__global__ void __launch_bounds__(512, 1)
lstm_kernel(const float* __restrict__ G, float* __restrict__ out) {
    extern __shared__ char smraw[];
    float4* W4  = (float4*)smraw;
    float* zbuf = (float*)(smraw + 16 * 512 * 16);
    float* hs   = zbuf + 512;

    const int dir = blockIdx.x & 1;
    const int b   = blockIdx.x >> 1;
    const int g   = threadIdx.x;

    const float4* Wg = g_WhhP4 + (size_t)dir * 32 * 512;
    for (int i = g; i < 16 * 512; i += 512) W4[i] = Wg[i];
    ull wr[32];
#pragma unroll
    for (int j = 0; j < 16; j++) {
        float4 w = Wg[(16 + j) * 512 + g];
        wr[2 * j]     = pack2(w.x, w.y);
        wr[2 * j + 1] = pack2(w.z, w.w);
    }
    if (g < 128) hs[g] = 0.f;
    float c = 0.f;
    __syncthreads();

    const float* gptr = G + (size_t)b * 512 * NG + dir * 512 + g;
    int trow = dir ? 511 : 0;
    const int tstep = dir ? -1 : 1;
    float gv = gptr[(size_t)trow * NG];

    for (int t = 0; t < 512; ++t) {
        float gcur = gv;
        if (t + 1 < 512) gv = gptr[(size_t)(trow + tstep) * NG];

        ull acc0 = 0ull, acc1 = 0ull;
#pragma unroll
        for (int k4 = 0; k4 < 16; k4++) {
            float4 w = W4[k4 * 512 + g];
            float4 h = *((const float4*)(hs + k4 * 4));
            ffma2(acc0, pack2(w.x, w.y), pack2(h.x, h.y));
            ffma2(acc1, pack2(w.z, w.w), pack2(h.z, h.w));
        }
#pragma unroll
        for (int j = 0; j < 16; j++) {
            float4 h = *((const float4*)(hs + (16 + j) * 4));
            ffma2(acc0, wr[2 * j],     pack2(h.x, h.y));
            ffma2(acc1, wr[2 * j + 1], pack2(h.z, h.w));
        }
        ull a = addf2(acc0, acc1);
        float lo, hi; unpack2(a, lo, hi);
        zbuf[g] = lo + hi + gcur;
        __syncthreads();

        if (g < 128) {
            float zi = zbuf[g], zf = zbuf[g + 128], zg = zbuf[g + 256], zo = zbuf[g + 384];
            c = sigf(zf) * c + sigf(zi) * tanhf_fast(zg);
            float h = sigf(zo) * tanhf_fast(c);
            hs[g] = h;
            out[((size_t)b * 512 + trow) * 256 + dir * 128 + g] = h;
        }
        __syncthreads();
        trow += tstep;
    }
}

// ---------------- launch ----------------
extern "C" void kernel_launch(void* const* d_in, const int* in_sizes, int n_in,
                              void* d_out, int out_size) {
    const float* x1w  = (const float*)d_in[0];
    const float* x1a0 = (const float*)d_in[1];
    const float* x1a1 = (const float*)d_in[2];
    const float* x2w  = (const float*)d_in[3];
    const float* x2a0 = (const float*)d_in[4];
    const float* x2a1 = (const float*)d_in[5];
    const float* x2a2 = (const float*)d_in[6];
    const unsigned char* x2mask = (const unsigned char*)d_in[8];
    const float* Wattn = (const float*)d_in[9];
    const float* vattn = (const float*)d_in[10];
    const float* Wihf = (const float*)d_in[11];
    const float* Whhf = (const float*)d_in[12];
    const float* bf   = (const float*)d_in[13];
    const float* Wihb = (const float*)d_in[14];
    const float* Whhb = (const float*)d_in[15];
    const float* bb   = (const float*)d_in[16];
    float* out = (float*)d_out;

    static bool attr_done = false;
    if (!attr_done) {
        cudaFuncSetAttribute(lstm_kernel, cudaFuncAttributeMaxDynamicSharedMemorySize, LSTM_SMEM);
        cudaFuncSetAttribute(hgemm<0>, cudaFuncAttributeMaxDynamicSharedMemorySize, HG_SMEM);
        cudaFuncSetAttribute(hgemm<1>, cudaFuncAttributeMaxDynamicSharedMemorySize, HG_SMEM);
        cudaFuncSetAttribute(hgemm<2>, cudaFuncAttributeMaxDynamicSharedMemorySize, HG_SMEM);
        cudaFuncSetAttribute(hgemm<3>, cudaFuncAttributeMaxDynamicSharedMemorySize, HG_SMEM);
        attr_done = true;
    }

    __half *A3, *W3, *R3A, *R3B, *AL3, *X2T3, *X13, *Wih3;
    float *vbig, *S, *bias, *Gm;
    cudaGetSymbolAddress((void**)&A3,   g_A3);
    cudaGetSymbolAddress((void**)&W3,   g_W3);
    cudaGetSymbolAddress((void**)&vbig, g_vbig);
    cudaGetSymbolAddress((void**)&R3A,  g_R3A);
    cudaGetSymbolAddress((void**)&R3B,  g_R3B);
    cudaGetSymbolAddress((void**)&S,    g_S);
    cudaGetSymbolAddress((void**)&AL3,  g_AL3);
    cudaGetSymbolAddress((void**)&X2T3, g_X2T3);
    cudaGetSymbolAddress((void**)&X13,  g_X13);
    cudaGetSymbolAddress((void**)&Wih3, g_Wih3);
    cudaGetSymbolAddress((void**)&bias, g_bias);
    cudaGetSymbolAddress((void**)&Gm,   g_G);

    // prep (launches 0..4) — R GEMM is launch #5 for ncu -s 5
    prep_A3     <<<(MR * KPADR + 255) / 256, 256>>>(x1w, x1a0, x1a1, x2w, x2a0, x2a1);
    prep_W3     <<<(NR * KPADR + 255) / 256, 256>>>(Wattn, vattn);
    prep_Wih3   <<<(NG * RNNK + 255) / 256, 256>>>(Wihf, Wihb, bf, bb);
    prep_headX13<<<(8192 * 512 + 255) / 256, 256>>>(x1a0, x1a1);
    {
        dim3 grid(16, 8, 48), blk(32, 32, 1);
        prep_X2T3<<<grid, blk>>>(x2a0, x2a1, x2a2);
    }

    // R = relu(A3 * W3^T) (+v for x2 rows): M=16384, N=768, K'=2496
    {
        dim3 grid(6, 128, 1);
        hgemm<1><<<grid, 256, HG_SMEM>>>(A3, W3, nullptr, nullptr,
            3 * KPADR, 3 * KPADR, 0, 39, 13, KPADR, 1, 0, 0, 0, 0, 0, 0, vbig, 8192);
    }
    // scores per (b,i): S = r1 * r2^T: M=512, N=512, K'=768 (256-col module slice per section)
    {
        dim3 grid(4, 4, 48);
        hgemm<0><<<grid, 256, HG_SMEM>>>(R3A, R3B, S, nullptr,
            3 * NR, 3 * NR, 512, 12, 4, NR, 3,
            (long)512 * 3 * NR, 256, (long)512 * 3 * NR, 256,
            (long)3 * 512 * 512, (long)512 * 512, nullptr, 0);
    }
    softmax_kernel<<<48 * 512, 256>>>(S, x2mask);
    // attn per (b,i): X13[:, 512 + i*256 ..] = alpha * x2_i^T: M=512, N=256, K'=1536
    {
        dim3 grid(2, 4, 48);
        hgemm<3><<<grid, 256, HG_SMEM>>>(AL3, X2T3, nullptr, X13 + 512,
            1536, 1536, 0, 24, 8, 512, 3,
            (long)3 * 512 * 1536, (long)512 * 1536,
            (long)256 * 1536, (long)16 * 256 * 1536,
            (long)512 * 3 * RNNK, 256, nullptr, 0);
    }
    // g_in = X13 * Wih3^T + bias: M=8192, N=1024, K'=3840
    {
        dim3 grid(8, 64, 1);
        hgemm<2><<<grid, 256, HG_SMEM>>>(X13, Wih3, Gm, nullptr,
            3 * RNNK, 3 * RNNK, NG, 60, 20, RNNK, 1, 0, 0, 0, 0, 0, 0, bias, 0);
    }
    prep_Whh<<<(2 * 32 * 512 + 255) / 256, 256>>>(Whhf, Whhb);
    lstm_kernel<<<32, 512, LSTM_SMEM>>>(Gm, out);
}

// round 9
// speedup vs baseline: 1.7782x; 1.2295x over previous
#include <cuda_runtime.h>
#include <cuda_fp16.h>
#include <cstdint>

typedef unsigned long long ull;

#define Bz   16
#define EMB  300
#define AH   256
#define KPADR 832              // padded 812 -> 832 (13*64)
#define NR   768               // 3*256
#define MR   16384
#define RNNK 1280
#define NG   1024
#define HH   128

// ---- scratch: split fp16 stored as [hi | lo] (2 sections); GEMM reads 3 logical sections
//      A-side pattern (hi,hi,lo) -> offsets (0,0,K);  B-side (hi,lo,hi) -> (0,K,0)
__device__ __half g_A3 [MR * (2*KPADR)];        // 16384 x 1664
__device__ __half g_W3 [NR * (2*KPADR)];        // 768 x 1664
__device__ float  g_vbig[NR];
__device__ __half g_R3A[8192 * (2*NR)];         // x1 rows: 8192 x 1536
__device__ __half g_R3B[8192 * (2*NR)];         // x2 rows (v-scaled)
__device__ float  g_S  [48 * 512 * 512];
__device__ __half g_AL3[48 * 512 * 1024];       // alpha [hi|lo]
__device__ __half g_X2T3[48 * 256 * 1024];      // x2^T [hi|lo], rows (i*16+b)*256+d
__device__ __half g_X13[8192 * (2*RNNK)];       // X1CAT [hi|lo], 8192 x 2560
__device__ __half g_Wih3[NG * (2*RNNK)];        // 1024 x 2560
__device__ float  g_bias[NG];
__device__ float  g_G  [8192 * NG];
__device__ uint2  g_WhhH[2 * 32 * 512];         // [dir][k4][gate]: 2x half2 (fp16 Whh)

// ---- helpers ----
__device__ __forceinline__ uint32_t s2u(const void* p) {
    uint32_t a;
    asm("{ .reg .u64 t; cvta.to.shared.u64 t, %1; cvt.u32.u64 %0, t; }" : "=r"(a) : "l"(p));
    return a;
}
__device__ __forceinline__ void split_h(float v, __half& h, __half& l) {
    h = __float2half_rn(v);
    l = __float2half_rn(v - __half2float(h));
}
__device__ __forceinline__ uint32_t swz(uint32_t off) {
    return off ^ ((off >> 3) & 0x70);
}
__device__ __forceinline__ void cp16(uint32_t dst, const void* src) {
    asm volatile("cp.async.cg.shared.global [%0], [%1], 16;" :: "r"(dst), "l"(src));
}
__device__ __forceinline__ void ldm_x4(uint32_t* r, uint32_t addr) {
    asm volatile("ldmatrix.sync.aligned.m8n8.x4.shared.b16 {%0,%1,%2,%3}, [%4];"
                 : "=r"(r[0]), "=r"(r[1]), "=r"(r[2]), "=r"(r[3]) : "r"(addr));
}
__device__ __forceinline__ void mma16816(float* c, const uint32_t* a, const uint32_t* b) {
    asm volatile(
        "mma.sync.aligned.m16n8k16.row.col.f32.f16.f16.f32 "
        "{%0,%1,%2,%3}, {%4,%5,%6,%7}, {%8,%9}, {%0,%1,%2,%3};"
        : "+f"(c[0]), "+f"(c[1]), "+f"(c[2]), "+f"(c[3])
        : "r"(a[0]), "r"(a[1]), "r"(a[2]), "r"(a[3]), "r"(b[0]), "r"(b[1]));
}
__device__ __forceinline__ __half2 u2h2(uint32_t u) {
    __half2 h; asm("mov.b32 %0, %1;" : "=r"(*(uint32_t*)&h) : "r"(u)); return h;
}

// ---------------- prep kernels ----------------
__global__ void prep_A3(const float* __restrict__ x1w, const float* __restrict__ x1a0,
                        const float* __restrict__ x1a1, const float* __restrict__ x2w,
                        const float* __restrict__ x2a0, const float* __restrict__ x2a1) {
    int idx = blockIdx.x * 256 + threadIdx.x;
    if (idx >= MR * KPADR) return;
    int r = idx / KPADR, c = idx - r * KPADR;
    float v = 0.f;
    if (c < 812) {
        int half = r >> 13, bl = r & 8191;
        if (c < 300)       v = (half ? x2w  : x1w )[(size_t)bl * EMB + c];
        else if (c < 556)  v = (half ? x2a0 : x1a0)[(size_t)bl * AH + (c - 300)];
        else               v = (half ? x2a1 : x1a1)[(size_t)bl * AH + (c - 556)];
    }
    __half h, l; split_h(v, h, l);
    __half* row = g_A3 + (size_t)r * (2 * KPADR) + c;
    row[0] = h; row[KPADR] = l;
}

__global__ void prep_W3(const float* __restrict__ Wattn, const float* __restrict__ vattn) {
    int idx = blockIdx.x * 256 + threadIdx.x;
    if (idx >= NR * KPADR) return;
    int g = idx / KPADR, c = idx - g * KPADR;
    int i = g >> 8, a = g & 255;
    float v = (a < 250 && c < 812) ? Wattn[((size_t)(i * 250 + a)) * 812 + c] : 0.f;
    __half h, l; split_h(v, h, l);
    __half* row = g_W3 + (size_t)g * (2 * KPADR) + c;
    row[0] = h; row[KPADR] = l;
    if (idx < NR) {
        int i2 = idx >> 8, a2 = idx & 255;
        g_vbig[idx] = (a2 < 250) ? vattn[i2 * 250 + a2] : 0.f;
    }
}

__global__ void prep_Wih3(const float* __restrict__ Wf, const float* __restrict__ Wb,
                          const float* __restrict__ bf, const float* __restrict__ bb) {
    int idx = blockIdx.x * 256 + threadIdx.x;
    if (idx >= NG * RNNK) return;
    int r = idx / RNNK, c = idx - r * RNNK;
    float v = (r < 512) ? Wf[(size_t)r * RNNK + c] : Wb[(size_t)(r - 512) * RNNK + c];
    __half h, l; split_h(v, h, l);
    __half* row = g_Wih3 + (size_t)r * (2 * RNNK) + c;
    row[0] = h; row[RNNK] = l;
    if (idx < NG) g_bias[idx] = (idx < 512) ? bf[idx] : bb[idx - 512];
}

__global__ void prep_headX13(const float* __restrict__ x1a0, const float* __restrict__ x1a1) {
    int idx = blockIdx.x * 256 + threadIdx.x;
    if (idx >= 8192 * 512) return;
    int r = idx >> 9, c = idx & 511;
    float v = (c < 256) ? x1a0[(size_t)r * AH + c] : x1a1[(size_t)r * AH + (c - 256)];
    __half h, l; split_h(v, h, l);
    __half* row = g_X13 + (size_t)r * (2 * RNNK) + c;
    row[0] = h; row[RNNK] = l;
}

// transpose x2_abstr_i [b][s][d] -> X2T3 rows (i*16+b)*256+d, cols s; [hi|lo]
__global__ void prep_X2T3(const float* __restrict__ a0, const float* __restrict__ a1,
                          const float* __restrict__ a2) {
    __shared__ float tile[32][33];
    int i = blockIdx.z >> 4, b = blockIdx.z & 15;
    int s0 = blockIdx.x * 32, d0 = blockIdx.y * 32;
    int tx = threadIdx.x, ty = threadIdx.y;
    const float* src = (i == 0) ? a0 : (i == 1) ? a1 : a2;
    tile[ty][tx] = src[((size_t)(b * 512 + s0 + ty)) * 256 + d0 + tx];
    __syncthreads();
    float v = tile[tx][ty];
    __half h, l; split_h(v, h, l);
    __half* row = g_X2T3 + ((size_t)((i * 16 + b) * 256 + d0 + ty)) * 1024 + s0 + tx;
    row[0] = h; row[512] = l;
}

// fp16 Whh, layout [dir][k4 0..31][gate 0..511] as uint2 = half2{4k4,4k4+1}, half2{4k4+2,4k4+3}
__global__ void prep_WhhH(const float* __restrict__ Whhf, const float* __restrict__ Whhb) {
    int idx = blockIdx.x * 256 + threadIdx.x;
    if (idx >= 2 * 32 * 512) return;
    int d = idx >> 14, k4 = (idx >> 9) & 31, g = idx & 511;
    const float* s = d ? Whhb : Whhf;
    size_t base = (size_t)g * HH + k4 * 4;
    __half2 p0 = __floats2half2_rn(s[base],     s[base + 1]);
    __half2 p1 = __floats2half2_rn(s[base + 2], s[base + 3]);
    uint2 u;
    u.x = *(uint32_t*)&p0;
    u.y = *(uint32_t*)&p1;
    g_WhhH[idx] = u;
}

// ---------------- HMMA GEMM: C[M,N] = A[M,K'] * B[N,K'] (fp16 NT, fp32 accum) ----------------
// K' = 3 logical sections mapped into [hi|lo] storage via (oA0..2 / oB0..2) column offsets.
// EPI: 0 scores f32 | 1 R split-out relu(+v) | 2 gin f32+bias | 3 X13 split-out
#define HG_SMEM (2 * 32768)

template <int EPI>
__global__ void __launch_bounds__(256, 2)
hgemm(const __half* __restrict__ A, const __half* __restrict__ B,
      float* __restrict__ Cf, __half* __restrict__ Cb,
      int ldA, int ldB, int ldC, int nkc, int kcPerSec,
      int oA0, int oA1, int oA2, int oB0, int oB1, int oB2,
      int zdiv, long sAb, long sAi, long sBb, long sBi, long sCb, long sCi,
      const float* __restrict__ evec, int rowSplit) {
    extern __shared__ __align__(1024) char smem[];
    const uint32_t su = s2u(smem);
    const int tid = threadIdx.x, lane = tid & 31, wid = tid >> 5;

    const int z = blockIdx.z, zi = z % zdiv, zb = z / zdiv;
    A += zb * sAb + zi * sAi;
    B += zb * sBb + zi * sBi;
    if (EPI == 0 || EPI == 2) Cf += zb * sCb + zi * sCi;
    if (EPI == 3)             Cb += zb * sCb + zi * sCi;
    const int m0 = blockIdx.y * 128, n0 = blockIdx.x * 128;
    const int r0 = tid >> 3, c16 = tid & 7;

    float acc[2][8][4];
#pragma unroll
    for (int i = 0; i < 2; i++)
#pragma unroll
        for (int j = 0; j < 8; j++)
#pragma unroll
            for (int q = 0; q < 4; q++) acc[i][j][q] = 0.f;

    const int wm = wid & 3, wn = wid >> 2;
    const int a_row = wm * 32 + (lane & 15);
    const int a_kb  = (lane >> 4) * 8;
    const int b_row = wn * 64 + ((lane >> 4) << 3) + (lane & 7);
    const int b_kb  = ((lane >> 3) & 1) * 8;

    auto issue = [&](int kc, int bsel) {
        int sec = kc / kcPerSec;
        int w = (kc - sec * kcPerSec) * 64;
        int colA = (sec == 0 ? oA0 : (sec == 1 ? oA1 : oA2)) + w;
        int colB = (sec == 0 ? oB0 : (sec == 1 ? oB1 : oB2)) + w;
        const __half* Ag = A + (size_t)(m0 + r0) * ldA + colA + c16 * 8;
        const __half* Bg = B + (size_t)(n0 + r0) * ldB + colB + c16 * 8;
        uint32_t sbase = su + bsel * 32768;
#pragma unroll
        for (int j = 0; j < 4; ++j) {
            uint32_t off = swz((r0 + 32 * j) * 128 + c16 * 16);
            cp16(sbase + off,          Ag + (size_t)(32 * j) * ldA);
            cp16(sbase + 16384 + off,  Bg + (size_t)(32 * j) * ldB);
        }
        asm volatile("cp.async.commit_group;" ::: "memory");
    };

    issue(0, 0);
    for (int kc = 0; kc < nkc; ++kc) {
        const int bsel = kc & 1;
        asm volatile("cp.async.wait_group 0;" ::: "memory");
        __syncthreads();
        if (kc + 1 < nkc) issue(kc + 1, bsel ^ 1);
        const uint32_t sAu = su + bsel * 32768;
        const uint32_t sBu = sAu + 16384;
#pragma unroll
        for (int ks = 0; ks < 4; ++ks) {
            uint32_t af[2][4], bf[4][4];
#pragma unroll
            for (int mi = 0; mi < 2; ++mi) {
                uint32_t off = (uint32_t)(a_row + mi * 16) * 128 + (a_kb + ks * 16) * 2;
                ldm_x4(af[mi], sAu + swz(off));
            }
#pragma unroll
            for (int nj = 0; nj < 4; ++nj) {
                uint32_t off = (uint32_t)(b_row + nj * 16) * 128 + (b_kb + ks * 16) * 2;
                ldm_x4(bf[nj], sBu + swz(off));
            }
#pragma unroll
            for (int mi = 0; mi < 2; ++mi)
#pragma unroll
                for (int ni = 0; ni < 8; ++ni)
                    mma16816(acc[mi][ni], af[mi], &bf[ni >> 1][(ni & 1) * 2]);
        }
    }

    const int tq = lane >> 2, tr = (lane & 3) * 2;
#pragma unroll
    for (int mi = 0; mi < 2; ++mi) {
#pragma unroll
        for (int h = 0; h < 2; ++h) {
            const int mg = m0 + wm * 32 + mi * 16 + h * 8 + tq;
#pragma unroll
            for (int ni = 0; ni < 8; ++ni) {
                const int nc = n0 + wn * 64 + ni * 8 + tr;
                float v0 = acc[mi][ni][h * 2], v1 = acc[mi][ni][h * 2 + 1];
                if (EPI == 0) {
                    *(float2*)(Cf + (size_t)mg * ldC + nc) = make_float2(v0, v1);
                } else if (EPI == 2) {
                    *(float2*)(Cf + (size_t)mg * ldC + nc) =
                        make_float2(v0 + evec[nc], v1 + evec[nc + 1]);
                } else if (EPI == 1) {
                    const bool isB = (mg >= rowSplit);
                    v0 = fmaxf(v0, 0.f); v1 = fmaxf(v1, 0.f);
                    if (isB) { v0 *= evec[nc]; v1 *= evec[nc + 1]; }
                    __half h0, l0, h1, l1;
                    split_h(v0, h0, l0); split_h(v1, h1, l1);
                    __half* base = isB ? g_R3B + (size_t)(mg - rowSplit) * (2 * NR) + nc
                                       : g_R3A + (size_t)mg * (2 * NR) + nc;
                    *(__half2*)(base)      = __halves2half2(h0, h1);
                    *(__half2*)(base + NR) = __halves2half2(l0, l1);
                } else {  // EPI == 3
                    __half h0, l0, h1, l1;
                    split_h(v0, h0, l0); split_h(v1, h1, l1);
                    __half* base = Cb + (size_t)mg * (2 * RNNK) + nc;
                    *(__half2*)(base)        = __halves2half2(h0, h1);
                    *(__half2*)(base + RNNK) = __halves2half2(l0, l1);
                }
            }
        }
    }
}

// ---------------- softmax: rows of 512 -> split fp16 alpha [hi|lo] ----------------
__global__ void softmax_kernel(const float* __restrict__ S, const unsigned char* __restrict__ x2mask) {
    const float NEGF = -3.4e38f;
    const float2* row = (const float2*)(S + (size_t)blockIdx.x * 512);
    int b = blockIdx.x / 1536;
    const unsigned char* mk = x2mask + b * 512;
    int t = threadIdx.x;
    float2 v = row[t];
    if (mk[2 * t])     v.x = NEGF;
    if (mk[2 * t + 1]) v.y = NEGF;
    __shared__ float red[8];
    float mx = fmaxf(v.x, v.y);
#pragma unroll
    for (int o = 16; o; o >>= 1) mx = fmaxf(mx, __shfl_xor_sync(0xffffffffu, mx, o));
    if ((t & 31) == 0) red[t >> 5] = mx;
    __syncthreads();
    float M = red[0];
#pragma unroll
    for (int i = 1; i < 8; i++) M = fmaxf(M, red[i]);
    __syncthreads();
    float e0 = __expf(v.x - M), e1 = __expf(v.y - M);
    float s = e0 + e1;
#pragma unroll
    for (int o = 16; o; o >>= 1) s += __shfl_xor_sync(0xffffffffu, s, o);
    if ((t & 31) == 0) red[t >> 5] = s;
    __syncthreads();
    float tot = red[0];
#pragma unroll
    for (int i = 1; i < 8; i++) tot += red[i];
    float inv = __fdividef(1.f, tot);
    float p0 = e0 * inv, p1 = e1 * inv;
    __half h0, l0, h1, l1;
    split_h(p0, h0, l0); split_h(p1, h1, l1);
    __half* base = g_AL3 + (size_t)blockIdx.x * 1024 + 2 * t;
    *(__half2*)(base)       = __halves2half2(h0, h1);
    *(__half2*)(base + 512) = __halves2half2(l0, l1);
}

// ---------------- BiLSTM: fp16 Whh, HFMA2 partial sums, f32 state/activations ----------------
__device__ __forceinline__ float sigf(float x) { return __fdividef(1.f, 1.f + __expf(-x)); }
__device__ __forceinline__ float tanhf_fast(float x) { return 1.f - __fdividef(2.f, __expf(2.f * x) + 1.f); }

// smem: Ws uint2[16][512] (64KB) + zbuf f32[512] (2KB) + hsH half[128] (256B)
#define LSTM_SMEM (16 * 512 * 8 + 512 * 4 + 256)

__global__ void __launch_bounds__(512, 1)
lstm_kernel(const float* __restrict__ G, float* __restrict__ out) {
    extern __shared__ char smraw[];
    uint2* Ws   = (uint2*)smraw;                       // [k4 0..15][512]
    float* zbuf = (float*)(smraw + 16 * 512 * 8);
    __half* hsH = (__half*)(smraw + 16 * 512 * 8 + 512 * 4);

    const int dir = blockIdx.x & 1;
    const int b   = blockIdx.x >> 1;
    const int g   = threadIdx.x;

    const uint2* Wg = g_WhhH + (size_t)dir * 32 * 512;
    for (int i = g; i < 16 * 512; i += 512) Ws[i] = Wg[i];
    uint2 wr[16];
#pragma unroll
    for (int j = 0; j < 16; j++) wr[j] = Wg[(16 + j) * 512 + g];
    if (g < 128) hsH[g] = __float2half(0.f);
    float c = 0.f;
    __syncthreads();

    const float* gptr = G + (size_t)b * 512 * NG + dir * 512 + g;
    int trow = dir ? 511 : 0;
    const int tstep = dir ? -1 : 1;
    float gv = gptr[(size_t)trow * NG];

    const __half2 z2 = __floats2half2_rn(0.f, 0.f);

    for (int t = 0; t < 512; ++t) {
        float gcur = gv;
        if (t + 1 < 512) gv = gptr[(size_t)(trow + tstep) * NG];

        // preload full h (128 half = 16 x uint4), broadcast reads
        uint4 hu[16];
        const uint4* hp = (const uint4*)hsH;
#pragma unroll
        for (int j = 0; j < 16; j++) hu[j] = hp[j];

        __half2 accA[4] = {z2, z2, z2, z2};
        __half2 accB[4] = {z2, z2, z2, z2};
#pragma unroll
        for (int k4 = 0; k4 < 16; k4++) {
            uint2 w = Ws[k4 * 512 + g];
            uint4 h4 = hu[k4 >> 1];
            uint32_t ha = (k4 & 1) ? h4.z : h4.x;
            uint32_t hb = (k4 & 1) ? h4.w : h4.y;
            accA[k4 & 3] = __hfma2(u2h2(w.x), u2h2(ha), accA[k4 & 3]);
            accB[k4 & 3] = __hfma2(u2h2(w.y), u2h2(hb), accB[k4 & 3]);
        }
#pragma unroll
        for (int j = 0; j < 16; j++) {
            int k4 = 16 + j;
            uint2 w = wr[j];
            uint4 h4 = hu[k4 >> 1];
            uint32_t ha = (k4 & 1) ? h4.z : h4.x;
            uint32_t hb = (k4 & 1) ? h4.w : h4.y;
            accA[j & 3] = __hfma2(u2h2(w.x), u2h2(ha), accA[j & 3]);
            accB[j & 3] = __hfma2(u2h2(w.y), u2h2(hb), accB[j & 3]);
        }
        float zsum = 0.f;
#pragma unroll
        for (int j = 0; j < 4; j++) {
            float2 fa = __half22float2(accA[j]);
            float2 fb = __half22float2(accB[j]);
            zsum += (fa.x + fa.y) + (fb.x + fb.y);
        }
        zbuf[g] = zsum + gcur;
        __syncthreads();

        if (g < 128) {
            float zi = zbuf[g], zf = zbuf[g + 128], zg = zbuf[g + 256], zo = zbuf[g + 384];
            c = sigf(zf) * c + sigf(zi) * tanhf_fast(zg);
            float h = sigf(zo) * tanhf_fast(c);
            hsH[g] = __float2half_rn(h);
            out[((size_t)b * 512 + trow) * 256 + dir * 128 + g] = h;
        }
        __syncthreads();
        trow += tstep;
    }
}

// ---------------- launch ----------------
extern "C" void kernel_launch(void* const* d_in, const int* in_sizes, int n_in,
                              void* d_out, int out_size) {
    const float* x1w  = (const float*)d_in[0];
    const float* x1a0 = (const float*)d_in[1];
    const float* x1a1 = (const float*)d_in[2];
    const float* x2w  = (const float*)d_in[3];
    const float* x2a0 = (const float*)d_in[4];
    const float* x2a1 = (const float*)d_in[5];
    const float* x2a2 = (const float*)d_in[6];
    const unsigned char* x2mask = (const unsigned char*)d_in[8];
    const float* Wattn = (const float*)d_in[9];
    const float* vattn = (const float*)d_in[10];
    const float* Wihf = (const float*)d_in[11];
    const float* Whhf = (const float*)d_in[12];
    const float* bf   = (const float*)d_in[13];
    const float* Wihb = (const float*)d_in[14];
    const float* Whhb = (const float*)d_in[15];
    const float* bb   = (const float*)d_in[16];
    float* out = (float*)d_out;

    static bool attr_done = false;
    if (!attr_done) {
        cudaFuncSetAttribute(lstm_kernel, cudaFuncAttributeMaxDynamicSharedMemorySize, LSTM_SMEM);
        cudaFuncSetAttribute(hgemm<0>, cudaFuncAttributeMaxDynamicSharedMemorySize, HG_SMEM);
        cudaFuncSetAttribute(hgemm<1>, cudaFuncAttributeMaxDynamicSharedMemorySize, HG_SMEM);
        cudaFuncSetAttribute(hgemm<2>, cudaFuncAttributeMaxDynamicSharedMemorySize, HG_SMEM);
        cudaFuncSetAttribute(hgemm<3>, cudaFuncAttributeMaxDynamicSharedMemorySize, HG_SMEM);
        attr_done = true;
    }

    __half *A3, *W3, *R3A, *R3B, *AL3, *X2T3, *X13, *Wih3;
    float *vbig, *S, *bias, *Gm;
    cudaGetSymbolAddress((void**)&A3,   g_A3);
    cudaGetSymbolAddress((void**)&W3,   g_W3);
    cudaGetSymbolAddress((void**)&vbig, g_vbig);
    cudaGetSymbolAddress((void**)&R3A,  g_R3A);
    cudaGetSymbolAddress((void**)&R3B,  g_R3B);
    cudaGetSymbolAddress((void**)&S,    g_S);
    cudaGetSymbolAddress((void**)&AL3,  g_AL3);
    cudaGetSymbolAddress((void**)&X2T3, g_X2T3);
    cudaGetSymbolAddress((void**)&X13,  g_X13);
    cudaGetSymbolAddress((void**)&Wih3, g_Wih3);
    cudaGetSymbolAddress((void**)&bias, g_bias);
    cudaGetSymbolAddress((void**)&Gm,   g_G);

    // launches 0..2, then the R GEMM at index 3 (ncu shows launch index 3)
    prep_A3  <<<(MR * KPADR + 255) / 256, 256>>>(x1w, x1a0, x1a1, x2w, x2a0, x2a1);
    prep_W3  <<<(NR * KPADR + 255) / 256, 256>>>(Wattn, vattn);
    prep_WhhH<<<(2 * 32 * 512 + 255) / 256, 256>>>(Whhf, Whhb);

    // R = relu(A3 * W3^T) (+v for x2 rows): M=16384, N=768, K'=2496
    {
        dim3 grid(6, 128, 1);
        hgemm<1><<<grid, 256, HG_SMEM>>>(A3, W3, nullptr, nullptr,
            2 * KPADR, 2 * KPADR, 0, 39, 13,
            0, 0, KPADR, 0, KPADR, 0,
            1, 0, 0, 0, 0, 0, 0, vbig, 8192);
    }

    prep_Wih3   <<<(NG * RNNK + 255) / 256, 256>>>(Wihf, Wihb, bf, bb);
    prep_headX13<<<(8192 * 512 + 255) / 256, 256>>>(x1a0, x1a1);
    {
        dim3 grid(16, 8, 48), blk(32, 32, 1);
        prep_X2T3<<<grid, blk>>>(x2a0, x2a1, x2a2);
    }

    // scores per (b,i): S = r1 * r2^T: M=512, N=512, K'=768 (module slice via +zi*256)
    {
        dim3 grid(4, 4, 48);
        hgemm<0><<<grid, 256, HG_SMEM>>>(R3A, R3B, S, nullptr,
            2 * NR, 2 * NR, 512, 12, 4,
            0, 0, NR, 0, NR, 0,
            3,
            (long)512 * 2 * NR, 256, (long)512 * 2 * NR, 256,
            (long)3 * 512 * 512, (long)512 * 512, nullptr, 0);
    }
    softmax_kernel<<<48 * 512, 256>>>(S, x2mask);
    // attn per (b,i): X13[:, 512 + i*256 ..] = alpha * x2_i^T: M=512, N=256, K'=1536
    {
        dim3 grid(2, 4, 48);
        hgemm<3><<<grid, 256, HG_SMEM>>>(AL3, X2T3, nullptr, X13 + 512,
            1024, 1024, 0, 24, 8,
            0, 0, 512, 0, 512, 0,
            3,
            (long)3 * 512 * 1024, (long)512 * 1024,
            (long)256 * 1024, (long)16 * 256 * 1024,
            (long)512 * 2 * RNNK, 256, nullptr, 0);
    }
    // g_in = X13 * Wih3^T + bias: M=8192, N=1024, K'=3840
    {
        dim3 grid(8, 64, 1);
        hgemm<2><<<grid, 256, HG_SMEM>>>(X13, Wih3, Gm, nullptr,
            2 * RNNK, 2 * RNNK, NG, 60, 20,
            0, 0, RNNK, 0, RNNK, 0,
            1, 0, 0, 0, 0, 0, 0, bias, 0);
    }
    lstm_kernel<<<32, 512, LSTM_SMEM>>>(Gm, out);
}

// round 10
// speedup vs baseline: 1.8102x; 1.0180x over previous
#include <cuda_runtime.h>
#include <cuda_fp16.h>
#include <cstdint>

typedef unsigned long long ull;

#define Bz   16
#define EMB  300
#define AH   256
#define KPADR 832              // padded 812 -> 832 (13*64)
#define NR   768               // 3*256
#define MR   16384
#define RNNK 1280
#define NG   1024
#define HH   128

// ---- scratch: split fp16 stored as [hi | lo]; GEMM computes Ah*Bh + Ah*Bl + Al*Bh ----
__device__ __half g_A3 [MR * (2*KPADR)];        // 16384 x 1664
__device__ __half g_W3 [NR * (2*KPADR)];        // 768 x 1664
__device__ float  g_vbig[NR];
__device__ __half g_R3A[8192 * (2*NR)];         // x1 rows: 8192 x 1536
__device__ __half g_R3B[8192 * (2*NR)];         // x2 rows (v-scaled)
__device__ float  g_S  [48 * 512 * 512];
__device__ __half g_AL3[48 * 512 * 1024];       // alpha [hi|lo]
__device__ __half g_X2T3[48 * 256 * 1024];      // x2^T [hi|lo], rows (i*16+b)*256+d
__device__ __half g_X13[8192 * (2*RNNK)];       // X1CAT [hi|lo], 8192 x 2560
__device__ __half g_Wih3[NG * (2*RNNK)];        // 1024 x 2560
__device__ float  g_bias[NG];
__device__ float  g_G  [8192 * NG];
__device__ uint2  g_WhhH[2 * 32 * 512];         // [dir][k4][gate]: 2x half2 (fp16 Whh)

// ---- helpers ----
__device__ __forceinline__ uint32_t s2u(const void* p) {
    uint32_t a;
    asm("{ .reg .u64 t; cvta.to.shared.u64 t, %1; cvt.u32.u64 %0, t; }" : "=r"(a) : "l"(p));
    return a;
}
__device__ __forceinline__ void split_h(float v, __half& h, __half& l) {
    h = __float2half_rn(v);
    l = __float2half_rn(v - __half2float(h));
}
__device__ __forceinline__ uint32_t swz(uint32_t off) {
    return off ^ ((off >> 3) & 0x70);
}
__device__ __forceinline__ void cp16(uint32_t dst, const void* src) {
    asm volatile("cp.async.cg.shared.global [%0], [%1], 16;" :: "r"(dst), "l"(src));
}
__device__ __forceinline__ void ldm_x4(uint32_t* r, uint32_t addr) {
    asm volatile("ldmatrix.sync.aligned.m8n8.x4.shared.b16 {%0,%1,%2,%3}, [%4];"
                 : "=r"(r[0]), "=r"(r[1]), "=r"(r[2]), "=r"(r[3]) : "r"(addr));
}
__device__ __forceinline__ void mma16816(float* c, const uint32_t* a, const uint32_t* b) {
    asm volatile(
        "mma.sync.aligned.m16n8k16.row.col.f32.f16.f16.f32 "
        "{%0,%1,%2,%3}, {%4,%5,%6,%7}, {%8,%9}, {%0,%1,%2,%3};"
        : "+f"(c[0]), "+f"(c[1]), "+f"(c[2]), "+f"(c[3])
        : "r"(a[0]), "r"(a[1]), "r"(a[2]), "r"(a[3]), "r"(b[0]), "r"(b[1]));
}
__device__ __forceinline__ __half2 u2h2(uint32_t u) {
    __half2 h; asm("mov.b32 %0, %1;" : "=r"(*(uint32_t*)&h) : "r"(u)); return h;
}

// ---------------- prep kernels ----------------
__global__ void prep_A3(const float* __restrict__ x1w, const float* __restrict__ x1a0,
                        const float* __restrict__ x1a1, const float* __restrict__ x2w,
                        const float* __restrict__ x2a0, const float* __restrict__ x2a1) {
    int idx = blockIdx.x * 256 + threadIdx.x;
    if (idx >= MR * KPADR) return;
    int r = idx / KPADR, c = idx - r * KPADR;
    float v = 0.f;
    if (c < 812) {
        int half = r >> 13, bl = r & 8191;
        if (c < 300)       v = (half ? x2w  : x1w )[(size_t)bl * EMB + c];
        else if (c < 556)  v = (half ? x2a0 : x1a0)[(size_t)bl * AH + (c - 300)];
        else               v = (half ? x2a1 : x1a1)[(size_t)bl * AH + (c - 556)];
    }
    __half h, l; split_h(v, h, l);
    __half* row = g_A3 + (size_t)r * (2 * KPADR) + c;
    row[0] = h; row[KPADR] = l;
}

__global__ void prep_W3(const float* __restrict__ Wattn, const float* __restrict__ vattn) {
    int idx = blockIdx.x * 256 + threadIdx.x;
    if (idx >= NR * KPADR) return;
    int g = idx / KPADR, c = idx - g * KPADR;
    int i = g >> 8, a = g & 255;
    float v = (a < 250 && c < 812) ? Wattn[((size_t)(i * 250 + a)) * 812 + c] : 0.f;
    __half h, l; split_h(v, h, l);
    __half* row = g_W3 + (size_t)g * (2 * KPADR) + c;
    row[0] = h; row[KPADR] = l;
    if (idx < NR) {
        int i2 = idx >> 8, a2 = idx & 255;
        g_vbig[idx] = (a2 < 250) ? vattn[i2 * 250 + a2] : 0.f;
    }
}

__global__ void prep_Wih3(const float* __restrict__ Wf, const float* __restrict__ Wb,
                          const float* __restrict__ bf, const float* __restrict__ bb) {
    int idx = blockIdx.x * 256 + threadIdx.x;
    if (idx >= NG * RNNK) return;
    int r = idx / RNNK, c = idx - r * RNNK;
    float v = (r < 512) ? Wf[(size_t)r * RNNK + c] : Wb[(size_t)(r - 512) * RNNK + c];
    __half h, l; split_h(v, h, l);
    __half* row = g_Wih3 + (size_t)r * (2 * RNNK) + c;
    row[0] = h; row[RNNK] = l;
    if (idx < NG) g_bias[idx] = (idx < 512) ? bf[idx] : bb[idx - 512];
}

__global__ void prep_headX13(const float* __restrict__ x1a0, const float* __restrict__ x1a1) {
    int idx = blockIdx.x * 256 + threadIdx.x;
    if (idx >= 8192 * 512) return;
    int r = idx >> 9, c = idx & 511;
    float v = (c < 256) ? x1a0[(size_t)r * AH + c] : x1a1[(size_t)r * AH + (c - 256)];
    __half h, l; split_h(v, h, l);
    __half* row = g_X13 + (size_t)r * (2 * RNNK) + c;
    row[0] = h; row[RNNK] = l;
}

// transpose x2_abstr_i [b][s][d] -> X2T3 rows (i*16+b)*256+d, cols s; [hi|lo]
__global__ void prep_X2T3(const float* __restrict__ a0, const float* __restrict__ a1,
                          const float* __restrict__ a2) {
    __shared__ float tile[32][33];
    int i = blockIdx.z >> 4, b = blockIdx.z & 15;
    int s0 = blockIdx.x * 32, d0 = blockIdx.y * 32;
    int tx = threadIdx.x, ty = threadIdx.y;
    const float* src = (i == 0) ? a0 : (i == 1) ? a1 : a2;
    tile[ty][tx] = src[((size_t)(b * 512 + s0 + ty)) * 256 + d0 + tx];
    __syncthreads();
    float v = tile[tx][ty];
    __half h, l; split_h(v, h, l);
    __half* row = g_X2T3 + ((size_t)((i * 16 + b) * 256 + d0 + ty)) * 1024 + s0 + tx;
    row[0] = h; row[512] = l;
}

// fp16 Whh, layout [dir][k4 0..31][gate 0..511] as uint2 = half2{4k4,4k4+1}, half2{4k4+2,4k4+3}
__global__ void prep_WhhH(const float* __restrict__ Whhf, const float* __restrict__ Whhb) {
    int idx = blockIdx.x * 256 + threadIdx.x;
    if (idx >= 2 * 32 * 512) return;
    int d = idx >> 14, k4 = (idx >> 9) & 31, g = idx & 511;
    const float* s = d ? Whhb : Whhf;
    size_t base = (size_t)g * HH + k4 * 4;
    __half2 p0 = __floats2half2_rn(s[base],     s[base + 1]);
    __half2 p1 = __floats2half2_rn(s[base + 2], s[base + 3]);
    uint2 u;
    u.x = *(uint32_t*)&p0;
    u.y = *(uint32_t*)&p1;
    g_WhhH[idx] = u;
}

// ---------------- HMMA GEMM: C = A * B^T with exact-split fp16 ----------------
// Per 64-col base-K chunk: load 4 panels (Ah, Al, Bh, Bl), compute Ah*Bh + Ah*Bl + Al*Bh.
// 3-stage cp.async pipeline. 128x128 CTA tile, 8 warps (warp tile 32x64).
// EPI: 0 scores f32 | 1 R split-out relu(+v) | 2 gin f32+bias | 3 X13 split-out
#define HG_STAGE 65536
#define HG_SMEM  (3 * HG_STAGE)

template <int EPI>
__global__ void __launch_bounds__(256, 1)
hgemm(const __half* __restrict__ A, const __half* __restrict__ B,
      float* __restrict__ Cf, __half* __restrict__ Cb,
      int ldA, int ldB, int ldC, int nkc, int loA, int loB,
      int zdiv, long sAb, long sAi, long sBb, long sBi, long sCb, long sCi,
      const float* __restrict__ evec, int rowSplit) {
    extern __shared__ __align__(1024) char smem[];
    const uint32_t su = s2u(smem);
    const int tid = threadIdx.x, lane = tid & 31, wid = tid >> 5;

    const int z = blockIdx.z, zi = z % zdiv, zb = z / zdiv;
    A += zb * sAb + zi * sAi;
    B += zb * sBb + zi * sBi;
    if (EPI == 0 || EPI == 2) Cf += zb * sCb + zi * sCi;
    if (EPI == 3)             Cb += zb * sCb + zi * sCi;
    const int m0 = blockIdx.y * 128, n0 = blockIdx.x * 128;
    const int r0 = tid >> 3, c16 = tid & 7;

    float acc[2][8][4];
#pragma unroll
    for (int i = 0; i < 2; i++)
#pragma unroll
        for (int j = 0; j < 8; j++)
#pragma unroll
            for (int q = 0; q < 4; q++) acc[i][j][q] = 0.f;

    const int wm = wid & 3, wn = wid >> 2;
    const int a_row = wm * 32 + (lane & 15);
    const int a_kb  = (lane >> 4) * 8;
    const int b_row = wn * 64 + ((lane >> 4) << 3) + (lane & 7);
    const int b_kb  = ((lane >> 3) & 1) * 8;

    // issue base-chunk kc into stage st: panels Ah/Al/Bh/Bl (16KB each)
    auto issue = [&](int kc, int st) {
        const __half* Ah = A + (size_t)(m0 + r0) * ldA + kc * 64 + c16 * 8;
        const __half* Bh = B + (size_t)(n0 + r0) * ldB + kc * 64 + c16 * 8;
        const __half* Al = Ah + loA;
        const __half* Bl = Bh + loB;
        uint32_t sb = su + st * HG_STAGE;
#pragma unroll
        for (int j = 0; j < 4; ++j) {
            uint32_t off = swz((r0 + 32 * j) * 128 + c16 * 16);
            cp16(sb + off,          Ah + (size_t)(32 * j) * ldA);
            cp16(sb + 16384 + off,  Al + (size_t)(32 * j) * ldA);
            cp16(sb + 32768 + off,  Bh + (size_t)(32 * j) * ldB);
            cp16(sb + 49152 + off,  Bl + (size_t)(32 * j) * ldB);
        }
        asm volatile("cp.async.commit_group;" ::: "memory");
    };

    issue(0, 0);
    issue(1, 1);
    for (int kc = 0; kc < nkc; ++kc) {
        const int st = kc % 3;
        asm volatile("cp.async.wait_group 1;" ::: "memory");
        __syncthreads();
        if (kc + 2 < nkc) issue(kc + 2, (kc + 2) % 3);
        const uint32_t sAh = su + st * HG_STAGE;
        const uint32_t sAl = sAh + 16384;
        const uint32_t sBh = sAh + 32768;
        const uint32_t sBl = sAh + 49152;
#pragma unroll
        for (int ks = 0; ks < 4; ++ks) {
            const uint32_t aoff0 = (uint32_t)(a_row) * 128 + (a_kb + ks * 16) * 2;
            const uint32_t aoff1 = (uint32_t)(a_row + 16) * 128 + (a_kb + ks * 16) * 2;
            uint32_t ah[2][4], al[2][4], bh[4][4], bl[4][4];
            ldm_x4(ah[0], sAh + swz(aoff0));
            ldm_x4(ah[1], sAh + swz(aoff1));
#pragma unroll
            for (int nj = 0; nj < 4; ++nj) {
                uint32_t off = (uint32_t)(b_row + nj * 16) * 128 + (b_kb + ks * 16) * 2;
                ldm_x4(bh[nj], sBh + swz(off));
            }
            // pass 1: Ah * Bh
#pragma unroll
            for (int mi = 0; mi < 2; ++mi)
#pragma unroll
                for (int ni = 0; ni < 8; ++ni)
                    mma16816(acc[mi][ni], ah[mi], &bh[ni >> 1][(ni & 1) * 2]);
            // pass 2: Ah * Bl
#pragma unroll
            for (int nj = 0; nj < 4; ++nj) {
                uint32_t off = (uint32_t)(b_row + nj * 16) * 128 + (b_kb + ks * 16) * 2;
                ldm_x4(bl[nj], sBl + swz(off));
            }
#pragma unroll
            for (int mi = 0; mi < 2; ++mi)
#pragma unroll
                for (int ni = 0; ni < 8; ++ni)
                    mma16816(acc[mi][ni], ah[mi], &bl[ni >> 1][(ni & 1) * 2]);
            // pass 3: Al * Bh
            ldm_x4(al[0], sAl + swz(aoff0));
            ldm_x4(al[1], sAl + swz(aoff1));
#pragma unroll
            for (int mi = 0; mi < 2; ++mi)
#pragma unroll
                for (int ni = 0; ni < 8; ++ni)
                    mma16816(acc[mi][ni], al[mi], &bh[ni >> 1][(ni & 1) * 2]);
        }
    }

    const int tq = lane >> 2, tr = (lane & 3) * 2;
#pragma unroll
    for (int mi = 0; mi < 2; ++mi) {
#pragma unroll
        for (int h = 0; h < 2; ++h) {
            const int mg = m0 + wm * 32 + mi * 16 + h * 8 + tq;
#pragma unroll
            for (int ni = 0; ni < 8; ++ni) {
                const int nc = n0 + wn * 64 + ni * 8 + tr;
                float v0 = acc[mi][ni][h * 2], v1 = acc[mi][ni][h * 2 + 1];
                if (EPI == 0) {
                    *(float2*)(Cf + (size_t)mg * ldC + nc) = make_float2(v0, v1);
                } else if (EPI == 2) {
                    *(float2*)(Cf + (size_t)mg * ldC + nc) =
                        make_float2(v0 + evec[nc], v1 + evec[nc + 1]);
                } else if (EPI == 1) {
                    const bool isB = (mg >= rowSplit);
                    v0 = fmaxf(v0, 0.f); v1 = fmaxf(v1, 0.f);
                    if (isB) { v0 *= evec[nc]; v1 *= evec[nc + 1]; }
                    __half h0, l0, h1, l1;
                    split_h(v0, h0, l0); split_h(v1, h1, l1);
                    __half* base = isB ? g_R3B + (size_t)(mg - rowSplit) * (2 * NR) + nc
                                       : g_R3A + (size_t)mg * (2 * NR) + nc;
                    *(__half2*)(base)      = __halves2half2(h0, h1);
                    *(__half2*)(base + NR) = __halves2half2(l0, l1);
                } else {  // EPI == 3
                    __half h0, l0, h1, l1;
                    split_h(v0, h0, l0); split_h(v1, h1, l1);
                    __half* base = Cb + (size_t)mg * (2 * RNNK) + nc;
                    *(__half2*)(base)        = __halves2half2(h0, h1);
                    *(__half2*)(base + RNNK) = __halves2half2(l0, l1);
                }
            }
        }
    }
}

// ---------------- softmax: rows of 512 -> split fp16 alpha [hi|lo] ----------------
__global__ void softmax_kernel(const float* __restrict__ S, const unsigned char* __restrict__ x2mask) {
    const float NEGF = -3.4e38f;
    const float2* row = (const float2*)(S + (size_t)blockIdx.x * 512);
    int b = blockIdx.x / 1536;
    const unsigned char* mk = x2mask + b * 512;
    int t = threadIdx.x;
    float2 v = row[t];
    if (mk[2 * t])     v.x = NEGF;
    if (mk[2 * t + 1]) v.y = NEGF;
    __shared__ float red[8];
    float mx = fmaxf(v.x, v.y);
#pragma unroll
    for (int o = 16; o; o >>= 1) mx = fmaxf(mx, __shfl_xor_sync(0xffffffffu, mx, o));
    if ((t & 31) == 0) red[t >> 5] = mx;
    __syncthreads();
    float M = red[0];
#pragma unroll
    for (int i = 1; i < 8; i++) M = fmaxf(M, red[i]);
    __syncthreads();
    float e0 = __expf(v.x - M), e1 = __expf(v.y - M);
    float s = e0 + e1;
#pragma unroll
    for (int o = 16; o; o >>= 1) s += __shfl_xor_sync(0xffffffffu, s, o);
    if ((t & 31) == 0) red[t >> 5] = s;
    __syncthreads();
    float tot = red[0];
#pragma unroll
    for (int i = 1; i < 8; i++) tot += red[i];
    float inv = __fdividef(1.f, tot);
    float p0 = e0 * inv, p1 = e1 * inv;
    __half h0, l0, h1, l1;
    split_h(p0, h0, l0); split_h(p1, h1, l1);
    __half* base = g_AL3 + (size_t)blockIdx.x * 1024 + 2 * t;
    *(__half2*)(base)       = __halves2half2(h0, h1);
    *(__half2*)(base + 512) = __halves2half2(l0, l1);
}

// ---------------- BiLSTM: fp16 Whh, HFMA2 partial sums, f32 state/activations ----------------
__device__ __forceinline__ float sigf(float x) { return __fdividef(1.f, 1.f + __expf(-x)); }
__device__ __forceinline__ float tanhf_fast(float x) { return 1.f - __fdividef(2.f, __expf(2.f * x) + 1.f); }

// smem: Ws uint2[16][512] (64KB) + zbuf f32[512] (2KB) + hsH half[128] (256B)
#define LSTM_SMEM (16 * 512 * 8 + 512 * 4 + 256)

__global__ void __launch_bounds__(512, 1)
lstm_kernel(const float* __restrict__ G, float* __restrict__ out) {
    extern __shared__ char smraw[];
    uint2* Ws   = (uint2*)smraw;                       // [k4 0..15][512]
    float* zbuf = (float*)(smraw + 16 * 512 * 8);
    __half* hsH = (__half*)(smraw + 16 * 512 * 8 + 512 * 4);

    const int dir = blockIdx.x & 1;
    const int b   = blockIdx.x >> 1;
    const int g   = threadIdx.x;

    const uint2* Wg = g_WhhH + (size_t)dir * 32 * 512;
    for (int i = g; i < 16 * 512; i += 512) Ws[i] = Wg[i];
    uint2 wr[16];
#pragma unroll
    for (int j = 0; j < 16; j++) wr[j] = Wg[(16 + j) * 512 + g];
    if (g < 128) hsH[g] = __float2half(0.f);
    float c = 0.f;
    __syncthreads();

    const float* gptr = G + (size_t)b * 512 * NG + dir * 512 + g;
    int trow = dir ? 511 : 0;
    const int tstep = dir ? -1 : 1;
    float gv = gptr[(size_t)trow * NG];

    const __half2 z2 = __floats2half2_rn(0.f, 0.f);

    for (int t = 0; t < 512; ++t) {
        float gcur = gv;
        if (t + 1 < 512) gv = gptr[(size_t)(trow + tstep) * NG];

        // preload full h (128 half = 16 x uint4), broadcast reads
        uint4 hu[16];
        const uint4* hp = (const uint4*)hsH;
#pragma unroll
        for (int j = 0; j < 16; j++) hu[j] = hp[j];

        __half2 accA[4] = {z2, z2, z2, z2};
        __half2 accB[4] = {z2, z2, z2, z2};
#pragma unroll
        for (int k4 = 0; k4 < 16; k4++) {
            uint2 w = Ws[k4 * 512 + g];
            uint4 h4 = hu[k4 >> 1];
            uint32_t ha = (k4 & 1) ? h4.z : h4.x;
            uint32_t hb = (k4 & 1) ? h4.w : h4.y;
            accA[k4 & 3] = __hfma2(u2h2(w.x), u2h2(ha), accA[k4 & 3]);
            accB[k4 & 3] = __hfma2(u2h2(w.y), u2h2(hb), accB[k4 & 3]);
        }
#pragma unroll
        for (int j = 0; j < 16; j++) {
            int k4 = 16 + j;
            uint2 w = wr[j];
            uint4 h4 = hu[k4 >> 1];
            uint32_t ha = (k4 & 1) ? h4.z : h4.x;
            uint32_t hb = (k4 & 1) ? h4.w : h4.y;
            accA[j & 3] = __hfma2(u2h2(w.x), u2h2(ha), accA[j & 3]);
            accB[j & 3] = __hfma2(u2h2(w.y), u2h2(hb), accB[j & 3]);
        }
        float zsum = 0.f;
#pragma unroll
        for (int j = 0; j < 4; j++) {
            float2 fa = __half22float2(accA[j]);
            float2 fb = __half22float2(accB[j]);
            zsum += (fa.x + fa.y) + (fb.x + fb.y);
        }
        zbuf[g] = zsum + gcur;
        __syncthreads();

        if (g < 128) {
            float zi = zbuf[g], zf = zbuf[g + 128], zg = zbuf[g + 256], zo = zbuf[g + 384];
            c = sigf(zf) * c + sigf(zi) * tanhf_fast(zg);
            float h = sigf(zo) * tanhf_fast(c);
            hsH[g] = __float2half_rn(h);
            out[((size_t)b * 512 + trow) * 256 + dir * 128 + g] = h;
        }
        __syncthreads();
        trow += tstep;
    }
}

// ---------------- launch ----------------
extern "C" void kernel_launch(void* const* d_in, const int* in_sizes, int n_in,
                              void* d_out, int out_size) {
    const float* x1w  = (const float*)d_in[0];
    const float* x1a0 = (const float*)d_in[1];
    const float* x1a1 = (const float*)d_in[2];
    const float* x2w  = (const float*)d_in[3];
    const float* x2a0 = (const float*)d_in[4];
    const float* x2a1 = (const float*)d_in[5];
    const float* x2a2 = (const float*)d_in[6];
    const unsigned char* x2mask = (const unsigned char*)d_in[8];
    const float* Wattn = (const float*)d_in[9];
    const float* vattn = (const float*)d_in[10];
    const float* Wihf = (const float*)d_in[11];
    const float* Whhf = (const float*)d_in[12];
    const float* bf   = (const float*)d_in[13];
    const float* Wihb = (const float*)d_in[14];
    const float* Whhb = (const float*)d_in[15];
    const float* bb   = (const float*)d_in[16];
    float* out = (float*)d_out;

    static bool attr_done = false;
    if (!attr_done) {
        cudaFuncSetAttribute(lstm_kernel, cudaFuncAttributeMaxDynamicSharedMemorySize, LSTM_SMEM);
        cudaFuncSetAttribute(hgemm<0>, cudaFuncAttributeMaxDynamicSharedMemorySize, HG_SMEM);
        cudaFuncSetAttribute(hgemm<1>, cudaFuncAttributeMaxDynamicSharedMemorySize, HG_SMEM);
        cudaFuncSetAttribute(hgemm<2>, cudaFuncAttributeMaxDynamicSharedMemorySize, HG_SMEM);
        cudaFuncSetAttribute(hgemm<3>, cudaFuncAttributeMaxDynamicSharedMemorySize, HG_SMEM);
        attr_done = true;
    }

    __half *A3, *W3, *R3A, *R3B, *AL3, *X2T3, *X13, *Wih3;
    float *vbig, *S, *bias, *Gm;
    cudaGetSymbolAddress((void**)&A3,   g_A3);
    cudaGetSymbolAddress((void**)&W3,   g_W3);
    cudaGetSymbolAddress((void**)&vbig, g_vbig);
    cudaGetSymbolAddress((void**)&R3A,  g_R3A);
    cudaGetSymbolAddress((void**)&R3B,  g_R3B);
    cudaGetSymbolAddress((void**)&S,    g_S);
    cudaGetSymbolAddress((void**)&AL3,  g_AL3);
    cudaGetSymbolAddress((void**)&X2T3, g_X2T3);
    cudaGetSymbolAddress((void**)&X13,  g_X13);
    cudaGetSymbolAddress((void**)&Wih3, g_Wih3);
    cudaGetSymbolAddress((void**)&bias, g_bias);
    cudaGetSymbolAddress((void**)&Gm,   g_G);

    // launches 0..2, then the R GEMM at index 3 (ncu profiles launch 3)
    prep_A3  <<<(MR * KPADR + 255) / 256, 256>>>(x1w, x1a0, x1a1, x2w, x2a0, x2a1);
    prep_W3  <<<(NR * KPADR + 255) / 256, 256>>>(Wattn, vattn);
    prep_WhhH<<<(2 * 32 * 512 + 255) / 256, 256>>>(Whhf, Whhb);

    // R = relu(A3 * W3^T) (+v for x2 rows): M=16384, N=768, baseK=832
    {
        dim3 grid(6, 128, 1);
        hgemm<1><<<grid, 256, HG_SMEM>>>(A3, W3, nullptr, nullptr,
            2 * KPADR, 2 * KPADR, 0, 13, KPADR, KPADR,
            1, 0, 0, 0, 0, 0, 0, vbig, 8192);
    }

    prep_Wih3   <<<(NG * RNNK + 255) / 256, 256>>>(Wihf, Wihb, bf, bb);
    prep_headX13<<<(8192 * 512 + 255) / 256, 256>>>(x1a0, x1a1);
    {
        dim3 grid(16, 8, 48), blk(32, 32, 1);
        prep_X2T3<<<grid, blk>>>(x2a0, x2a1, x2a2);
    }

    // scores per (b,i): S = r1 * r2^T: M=512, N=512, baseK=256 (module slice via +zi*256)
    {
        dim3 grid(4, 4, 48);
        hgemm<0><<<grid, 256, HG_SMEM>>>(R3A, R3B, S, nullptr,
            2 * NR, 2 * NR, 512, 4, NR, NR,
            3,
            (long)512 * 2 * NR, 256, (long)512 * 2 * NR, 256,
            (long)3 * 512 * 512, (long)512 * 512, nullptr, 0);
    }
    softmax_kernel<<<48 * 512, 256>>>(S, x2mask);
    // attn per (b,i): X13[:, 512 + i*256 ..] = alpha * x2_i^T: M=512, N=256, baseK=512
    {
        dim3 grid(2, 4, 48);
        hgemm<3><<<grid, 256, HG_SMEM>>>(AL3, X2T3, nullptr, X13 + 512,
            1024, 1024, 0, 8, 512, 512,
            3,
            (long)3 * 512 * 1024, (long)512 * 1024,
            (long)256 * 1024, (long)16 * 256 * 1024,
            (long)512 * 2 * RNNK, 256, nullptr, 0);
    }
    // g_in = X13 * Wih3^T + bias: M=8192, N=1024, baseK=1280
    {
        dim3 grid(8, 64, 1);
        hgemm<2><<<grid, 256, HG_SMEM>>>(X13, Wih3, Gm, nullptr,
            2 * RNNK, 2 * RNNK, NG, 20, RNNK, RNNK,
            1, 0, 0, 0, 0, 0, 0, bias, 0);
    }
    lstm_kernel<<<32, 512, LSTM_SMEM>>>(Gm, out);
}